// round 1
// baseline (speedup 1.0000x reference)
#include <cuda_runtime.h>
#include <math.h>

// ---------------- problem constants ----------------
#define S_LEN 2048
#define HID   2048
#define NH    16
#define HD    128
#define NQKV  6144   // 3 * HID
#define ROT   32

// ---------------- scratch (device globals; no runtime alloc) ----------------
__device__ float g_mixed[(size_t)S_LEN * NQKV];        // 48 MB
__device__ float g_q[(size_t)NH * S_LEN * HD];         // 16 MB
__device__ float g_k[(size_t)NH * S_LEN * HD];         // 16 MB
__device__ float g_v[(size_t)NH * S_LEN * HD];         // 16 MB
__device__ float g_ctx[(size_t)S_LEN * HID];           // 16 MB

// ---------------- SGEMM: C[M,N] = A[M,K] @ B[K,N] + bias[N] ----------------
// 128x128 block tile, BK=16, 256 threads, 8x8 register tile per thread.
#define BM 128
#define BN 128
#define BK 16
#define TM 8
#define TN 8

__global__ __launch_bounds__(256) void sgemm_bias_kernel(
    const float* __restrict__ A, const float* __restrict__ B,
    const float* __restrict__ bias, float* __restrict__ C,
    int M, int N, int K)
{
    __shared__ float As[BK][BM];   // transposed A tile
    __shared__ float Bs[BK][BN];

    const int bx = blockIdx.x;     // N tile
    const int by = blockIdx.y;     // M tile
    const int tid = threadIdx.x;

    const int tr = tid / (BN / TN);   // 0..15
    const int tc = tid % (BN / TN);   // 0..15

    // A tile load mapping: 128x16 floats = 512 float4, 2 per thread
    const int aRow = tid / 4;          // 0..63
    const int aCol = (tid % 4) * 4;    // 0,4,8,12
    // B tile load mapping: 16x128 floats = 512 float4, 2 per thread
    const int bRow = tid / 32;         // 0..7
    const int bCol = (tid % 32) * 4;   // 0..124

    const float* Ab = A + (size_t)by * BM * K;
    const float* Bb = B + (size_t)bx * BN;

    float acc[TM][TN];
    #pragma unroll
    for (int i = 0; i < TM; i++)
        #pragma unroll
        for (int j = 0; j < TN; j++) acc[i][j] = 0.0f;

    for (int k0 = 0; k0 < K; k0 += BK) {
        #pragma unroll
        for (int p = 0; p < 2; p++) {
            int r = aRow + p * 64;
            float4 t = *reinterpret_cast<const float4*>(&Ab[(size_t)r * K + k0 + aCol]);
            As[aCol + 0][r] = t.x;
            As[aCol + 1][r] = t.y;
            As[aCol + 2][r] = t.z;
            As[aCol + 3][r] = t.w;
        }
        #pragma unroll
        for (int p = 0; p < 2; p++) {
            int r = bRow + p * 8;
            *reinterpret_cast<float4*>(&Bs[r][bCol]) =
                *reinterpret_cast<const float4*>(&Bb[(size_t)(k0 + r) * N + bCol]);
        }
        __syncthreads();

        #pragma unroll
        for (int k = 0; k < BK; k++) {
            float ra[TM], rb[TN];
            #pragma unroll
            for (int i = 0; i < TM; i++) ra[i] = As[k][tr * TM + i];
            #pragma unroll
            for (int j = 0; j < TN; j++) rb[j] = Bs[k][tc * TN + j];
            #pragma unroll
            for (int i = 0; i < TM; i++)
                #pragma unroll
                for (int j = 0; j < TN; j++)
                    acc[i][j] += ra[i] * rb[j];
        }
        __syncthreads();
    }

    // epilogue: + bias, vectorized store
    #pragma unroll
    for (int i = 0; i < TM; i++) {
        int row = by * BM + tr * TM + i;
        float* Crow = C + (size_t)row * N + bx * BN;
        #pragma unroll
        for (int j = 0; j < TN; j += 4) {
            int col = tc * TN + j;
            int gcol = bx * BN + col;
            float4 o;
            o.x = acc[i][j + 0] + bias[gcol + 0];
            o.y = acc[i][j + 1] + bias[gcol + 1];
            o.z = acc[i][j + 2] + bias[gcol + 2];
            o.w = acc[i][j + 3] + bias[gcol + 3];
            *reinterpret_cast<float4*>(Crow + col) = o;
        }
    }
}

// ---------------- RoPE + scatter to head-major Q/K/V ----------------
// mixed: [s, 6144] where col = head*384 + {0:q,128:k,256:v} + d
// outputs: [head][s][d]
__global__ __launch_bounds__(128) void qkv_rope_kernel(
    const float* __restrict__ mixed,
    float* __restrict__ Q, float* __restrict__ K, float* __restrict__ V)
{
    const int t = blockIdx.x;
    const int h = blockIdx.y;
    const int d = threadIdx.x;

    const float* base = mixed + (size_t)t * NQKV + h * (3 * HD);
    float q = base[d];
    float k = base[HD + d];
    float v = base[2 * HD + d];

    if (d < ROT) {
        const int i = d & 15;  // index into inv_freq (half = 16)
        float inv_freq = 1.0f / powf(10000.0f, (float)(2 * i) * (1.0f / (float)ROT));
        float ang = (float)t * inv_freq;
        float s, c;
        sincosf(ang, &s, &c);
        if (d < 16) {
            q = q * c - base[d + 16] * s;
            k = k * c - base[HD + d + 16] * s;
        } else {
            q = q * c + base[d - 16] * s;
            k = k * c + base[HD + d - 16] * s;
        }
    }

    size_t off = ((size_t)h * S_LEN + t) * HD + d;
    Q[off] = q;
    K[off] = k;
    V[off] = v;
}

// ---------------- flash attention (fp32, causal) ----------------
// One block: (head, 64-row query tile). 256 threads (16x16).
// smem: Qs[64][128], Kst[128][65] (k-major, padded), Vs[64][128], Ps[64][64]
#define FM 64
#define FN 64
#define KST_LD 65
#define FLASH_SMEM ((FM*HD + HD*KST_LD + FN*HD + FM*FN) * 4)

__global__ __launch_bounds__(256) void flash_attn_kernel(
    const float* __restrict__ Q, const float* __restrict__ K,
    const float* __restrict__ V, float* __restrict__ ctx)
{
    extern __shared__ float smem[];
    float* Qs  = smem;                       // [64][128]
    float* Kst = Qs  + FM * HD;              // [128][65]
    float* Vs  = Kst + HD * KST_LD;          // [64][128]
    float* Ps  = Vs  + FN * HD;              // [64][64]

    const int h   = blockIdx.y;
    const int m0  = blockIdx.x * FM;
    const int tid = threadIdx.x;
    const int tr  = tid >> 4;   // 0..15 -> 4 query rows each
    const int tc  = tid & 15;   // 0..15

    const float* Qh = Q + ((size_t)h * S_LEN + m0) * HD;
    const float* Kh = K + (size_t)h * S_LEN * HD;
    const float* Vh = V + (size_t)h * S_LEN * HD;

    // load Q tile (float4, coalesced)
    for (int idx = tid; idx < FM * HD / 4; idx += 256) {
        int r = idx >> 5;
        int c = (idx & 31) << 2;
        *reinterpret_cast<float4*>(Qs + r * HD + c) =
            *reinterpret_cast<const float4*>(Qh + (size_t)r * HD + c);
    }

    float m_i[4], l_i[4], o[4][8];
    #pragma unroll
    for (int i = 0; i < 4; i++) {
        m_i[i] = -1e30f;
        l_i[i] = 0.0f;
        #pragma unroll
        for (int x = 0; x < 8; x++) o[i][x] = 0.0f;
    }

    const float scale = 0.08838834764831845f;  // 1/sqrt(128)

    for (int n0 = 0; n0 <= m0; n0 += FN) {
        __syncthreads();  // protect Kst/Vs/Ps reuse (and Q store on iter 0)

        // load K tile transposed -> Kst[k][key] (pad 65: conflict-free)
        for (int idx = tid; idx < FN * HD; idx += 256) {
            int r = idx >> 7;     // key within tile
            int c = idx & 127;    // dim
            Kst[c * KST_LD + r] = Kh[(size_t)(n0 + r) * HD + c];
        }
        // load V tile (row-major, float4)
        for (int idx = tid; idx < FN * HD / 4; idx += 256) {
            int r = idx >> 5;
            int c = (idx & 31) << 2;
            *reinterpret_cast<float4*>(Vs + r * HD + c) =
                *reinterpret_cast<const float4*>(Vh + (size_t)(n0 + r) * HD + c);
        }
        __syncthreads();

        // S = Q K^T : thread covers rows tr*4+i, keys tc + 16*j
        float s[4][4];
        #pragma unroll
        for (int i = 0; i < 4; i++)
            #pragma unroll
            for (int j = 0; j < 4; j++) s[i][j] = 0.0f;

        #pragma unroll 4
        for (int k = 0; k < HD; k++) {
            float qa[4], kb[4];
            #pragma unroll
            for (int i = 0; i < 4; i++) qa[i] = Qs[(tr * 4 + i) * HD + k];
            #pragma unroll
            for (int j = 0; j < 4; j++) kb[j] = Kst[k * KST_LD + tc + 16 * j];
            #pragma unroll
            for (int i = 0; i < 4; i++)
                #pragma unroll
                for (int j = 0; j < 4; j++) s[i][j] += qa[i] * kb[j];
        }

        // scale + causal mask
        #pragma unroll
        for (int i = 0; i < 4; i++) {
            int row = m0 + tr * 4 + i;
            #pragma unroll
            for (int j = 0; j < 4; j++) {
                int key = n0 + tc + 16 * j;
                s[i][j] = (key > row) ? -1e30f : s[i][j] * scale;
            }
        }

        // online softmax per row; row stats reduced over the 16 tc lanes
        #pragma unroll
        for (int i = 0; i < 4; i++) {
            float mx = fmaxf(fmaxf(s[i][0], s[i][1]), fmaxf(s[i][2], s[i][3]));
            #pragma unroll
            for (int off = 8; off > 0; off >>= 1)
                mx = fmaxf(mx, __shfl_xor_sync(0xffffffffu, mx, off, 16));
            float m_new = fmaxf(m_i[i], mx);
            float alpha = __expf(m_i[i] - m_new);
            m_i[i] = m_new;

            float rs = 0.0f;
            #pragma unroll
            for (int j = 0; j < 4; j++) {
                float p = __expf(s[i][j] - m_new);
                s[i][j] = p;
                rs += p;
            }
            #pragma unroll
            for (int off = 8; off > 0; off >>= 1)
                rs += __shfl_xor_sync(0xffffffffu, rs, off, 16);

            l_i[i] = l_i[i] * alpha + rs;
            #pragma unroll
            for (int x = 0; x < 8; x++) o[i][x] *= alpha;
            #pragma unroll
            for (int j = 0; j < 4; j++)
                Ps[(tr * 4 + i) * FN + tc + 16 * j] = s[i][j];
        }
        __syncthreads();

        // O += P @ V : thread covers rows tr*4+i, dims tc*8 .. tc*8+7
        #pragma unroll 2
        for (int jj = 0; jj < FN; jj++) {
            float pv[4];
            #pragma unroll
            for (int i = 0; i < 4; i++) pv[i] = Ps[(tr * 4 + i) * FN + jj];
            float4 v0 = *reinterpret_cast<float4*>(Vs + jj * HD + tc * 8);
            float4 v1 = *reinterpret_cast<float4*>(Vs + jj * HD + tc * 8 + 4);
            #pragma unroll
            for (int i = 0; i < 4; i++) {
                o[i][0] += pv[i] * v0.x;  o[i][1] += pv[i] * v0.y;
                o[i][2] += pv[i] * v0.z;  o[i][3] += pv[i] * v0.w;
                o[i][4] += pv[i] * v1.x;  o[i][5] += pv[i] * v1.y;
                o[i][6] += pv[i] * v1.z;  o[i][7] += pv[i] * v1.w;
            }
        }
    }

    // write ctx[s, h*128 + d] = O / l
    #pragma unroll
    for (int i = 0; i < 4; i++) {
        int row = m0 + tr * 4 + i;
        float inv = 1.0f / l_i[i];
        float4 r0, r1;
        r0.x = o[i][0] * inv;  r0.y = o[i][1] * inv;
        r0.z = o[i][2] * inv;  r0.w = o[i][3] * inv;
        r1.x = o[i][4] * inv;  r1.y = o[i][5] * inv;
        r1.z = o[i][6] * inv;  r1.w = o[i][7] * inv;
        float* dst = ctx + (size_t)row * HID + h * HD + tc * 8;
        *reinterpret_cast<float4*>(dst)     = r0;
        *reinterpret_cast<float4*>(dst + 4) = r1;
    }
}

// ---------------- launch ----------------
extern "C" void kernel_launch(void* const* d_in, const int* in_sizes, int n_in,
                              void* d_out, int out_size)
{
    const float* hidden  = (const float*)d_in[0];
    const float* W_qkv   = (const float*)d_in[1];
    const float* b_qkv   = (const float*)d_in[2];
    const float* W_dense = (const float*)d_in[3];
    const float* b_dense = (const float*)d_in[4];
    // d_in[5] = attention_mask (causal, known analytically; not read)
    float* out = (float*)d_out;

    float *mixed, *q, *k, *v, *ctx;
    cudaGetSymbolAddress((void**)&mixed, g_mixed);
    cudaGetSymbolAddress((void**)&q,     g_q);
    cudaGetSymbolAddress((void**)&k,     g_k);
    cudaGetSymbolAddress((void**)&v,     g_v);
    cudaGetSymbolAddress((void**)&ctx,   g_ctx);

    cudaFuncSetAttribute(flash_attn_kernel,
                         cudaFuncAttributeMaxDynamicSharedMemorySize, FLASH_SMEM);

    // 1) QKV projection (+bias)
    dim3 g1(NQKV / BN, S_LEN / BM);
    sgemm_bias_kernel<<<g1, 256>>>(hidden, W_qkv, b_qkv, mixed, S_LEN, NQKV, HID);

    // 2) RoPE + scatter to head-major Q/K/V
    qkv_rope_kernel<<<dim3(S_LEN, NH), 128>>>(mixed, q, k, v);

    // 3) causal flash attention
    flash_attn_kernel<<<dim3(S_LEN / FM, NH), 256, FLASH_SMEM>>>(q, k, v, ctx);

    // 4) dense projection (+bias)
    dim3 g2(HID / BN, S_LEN / BM);
    sgemm_bias_kernel<<<g2, 256>>>(ctx, W_dense, b_dense, out, S_LEN, HID, HID);
}

// round 3
// speedup vs baseline: 1.5428x; 1.5428x over previous
#include <cuda_runtime.h>
#include <cuda_bf16.h>
#include <cstdint>
#include <math.h>

using std::uint32_t;

// ---------------- problem constants ----------------
#define S_LEN 2048
#define HID   2048
#define NH    16
#define HD    128
#define NQKV  6144   // 3 * HID
#define ROT   32

typedef __nv_bfloat16 bf16;

// ---------------- scratch (device globals; no runtime alloc) ----------------
__device__ float g_mixed[(size_t)S_LEN * NQKV];        // 48 MB
__device__ float g_q[(size_t)NH * S_LEN * HD];         // 16 MB
__device__ float g_k[(size_t)NH * S_LEN * HD];         // 16 MB
__device__ float g_v[(size_t)NH * S_LEN * HD];         // 16 MB
__device__ float g_ctx[(size_t)S_LEN * HID];           // 16 MB

// bf16 hi/lo splits
__device__ bf16 g_ah[(size_t)S_LEN * HID];             // hidden hi
__device__ bf16 g_al[(size_t)S_LEN * HID];             // hidden lo
__device__ bf16 g_bh[(size_t)HID * NQKV];              // W_qkv hi
__device__ bf16 g_bl[(size_t)HID * NQKV];              // W_qkv lo
__device__ bf16 g_wh[(size_t)HID * HID];               // W_dense hi
__device__ bf16 g_wl[(size_t)HID * HID];               // W_dense lo
__device__ bf16 g_ch[(size_t)S_LEN * HID];             // ctx hi
__device__ bf16 g_cl[(size_t)S_LEN * HID];             // ctx lo

// ---------------- fp32 -> bf16 hi/lo split ----------------
__global__ __launch_bounds__(256) void split_bf16_kernel(
    const float* __restrict__ x, bf16* __restrict__ hi, bf16* __restrict__ lo, int n4)
{
    int i = blockIdx.x * blockDim.x + threadIdx.x;
    if (i >= n4) return;
    float4 v = reinterpret_cast<const float4*>(x)[i];
    bf16 h0 = __float2bfloat16(v.x);
    bf16 h1 = __float2bfloat16(v.y);
    bf16 h2 = __float2bfloat16(v.z);
    bf16 h3 = __float2bfloat16(v.w);
    bf16 l0 = __float2bfloat16(v.x - __bfloat162float(h0));
    bf16 l1 = __float2bfloat16(v.y - __bfloat162float(h1));
    bf16 l2 = __float2bfloat16(v.z - __bfloat162float(h2));
    bf16 l3 = __float2bfloat16(v.w - __bfloat162float(h3));
    __nv_bfloat162* hp = reinterpret_cast<__nv_bfloat162*>(hi);
    __nv_bfloat162* lp = reinterpret_cast<__nv_bfloat162*>(lo);
    hp[2 * i]     = __nv_bfloat162(h0, h1);
    hp[2 * i + 1] = __nv_bfloat162(h2, h3);
    lp[2 * i]     = __nv_bfloat162(l0, l1);
    lp[2 * i + 1] = __nv_bfloat162(l2, l3);
}

// ---------------- tensor-core GEMM (bf16x3, fp32 accum) ----------------
// C[M,N] = A[M,K] @ B[K,N] + bias, via Ah*Bh + Ah*Bl + Al*Bh.
// 128x128 block tile, BK=32, 256 threads (8 warps, 2x4), warp tile 64x32.

#define GBK 32
// smem layout (bf16 element offsets, per buffer)
#define SA     40                    // A row stride (32 data + 8 pad)
#define SB     136                   // B row stride (128 data + 8 pad)
#define OAH    0
#define OAL    (128 * SA)            // 5120
#define OBH    (2 * 128 * SA)        // 10240
#define OBL    (OBH + 32 * SB)       // 14592
#define BUFSZ  (OBL + 32 * SB)       // 18944 bf16 = 37888 B
#define GEMM_SMEM (2 * BUFSZ * 2)    // 75776 B

__device__ __forceinline__ void cp_async16(void* smem_dst, const void* gmem_src) {
    uint32_t s = (uint32_t)__cvta_generic_to_shared(smem_dst);
    asm volatile("cp.async.cg.shared.global [%0], [%1], 16;\n" :: "r"(s), "l"(gmem_src));
}
__device__ __forceinline__ void cp_commit() {
    asm volatile("cp.async.commit_group;\n");
}
template <int N>
__device__ __forceinline__ void cp_wait() {
    asm volatile("cp.async.wait_group %0;\n" :: "n"(N));
}

__device__ __forceinline__ void mma16816(float* c, const uint32_t* a, const uint32_t* b) {
    asm volatile(
        "mma.sync.aligned.m16n8k16.row.col.f32.bf16.bf16.f32 "
        "{%0,%1,%2,%3}, {%4,%5,%6,%7}, {%8,%9}, {%0,%1,%2,%3};\n"
        : "+f"(c[0]), "+f"(c[1]), "+f"(c[2]), "+f"(c[3])
        : "r"(a[0]), "r"(a[1]), "r"(a[2]), "r"(a[3]), "r"(b[0]), "r"(b[1]));
}

__global__ __launch_bounds__(256, 1) void mma_gemm_bf16x3(
    const bf16* __restrict__ Ah, const bf16* __restrict__ Al,
    const bf16* __restrict__ Bh, const bf16* __restrict__ Bl,
    const float* __restrict__ bias, float* __restrict__ C,
    int M, int N, int K)
{
    extern __shared__ __align__(16) unsigned char smraw[];
    bf16* sm = reinterpret_cast<bf16*>(smraw);

    const int bx = blockIdx.x;   // N tile
    const int by = blockIdx.y;   // M tile
    const int tid = threadIdx.x;
    const int warp = tid >> 5;
    const int lane = tid & 31;
    const int warp_m = warp >> 2;      // 0..1
    const int warp_n = warp & 3;       // 0..3
    const int g  = lane >> 2;          // 0..7
    const int tg = lane & 3;           // 0..3

    const int nstage = K / GBK;

    float acc[4][4][4];
    #pragma unroll
    for (int i = 0; i < 4; i++)
        #pragma unroll
        for (int j = 0; j < 4; j++)
            #pragma unroll
            for (int x = 0; x < 4; x++) acc[i][j][x] = 0.0f;

    // ---- async-copy one K stage into buffer (s & 1) ----
    auto issue = [&](int s) {
        const int k0 = s * GBK;
        bf16* buf = sm + (s & 1) * BUFSZ;
        // A tiles: 128 rows x 4 chunks of 16B
        #pragma unroll
        for (int q = tid; q < 512; q += 256) {
            int r = q >> 2, c = q & 3;
            size_t goff = (size_t)(by * 128 + r) * K + k0 + c * 8;
            int soff = r * SA + c * 8;
            cp_async16(buf + OAH + soff, Ah + goff);
            cp_async16(buf + OAL + soff, Al + goff);
        }
        // B tiles: 32 rows x 16 chunks of 16B
        #pragma unroll
        for (int q = tid; q < 512; q += 256) {
            int kr = q >> 4, c = q & 15;
            size_t goff = (size_t)(k0 + kr) * N + bx * 128 + c * 8;
            int soff = kr * SB + c * 8;
            cp_async16(buf + OBH + soff, Bh + goff);
            cp_async16(buf + OBL + soff, Bl + goff);
        }
    };

    issue(0);
    cp_commit();

    for (int s = 0; s < nstage; s++) {
        if (s + 1 < nstage) {
            issue(s + 1);
            cp_commit();
            cp_wait<1>();
        } else {
            cp_wait<0>();
        }
        __syncthreads();

        const bf16* buf = sm + (s & 1) * BUFSZ;
        const unsigned short* bs = reinterpret_cast<const unsigned short*>(buf);

        #pragma unroll
        for (int ks = 0; ks < GBK; ks += 16) {
            uint32_t ah[4][4], al[4][4], bh[4][2], bl[4][2];
            #pragma unroll
            for (int i = 0; i < 4; i++) {
                int base_m = warp_m * 64 + i * 16;
                int ra = (base_m + g) * SA + ks + 2 * tg;
                ah[i][0] = *reinterpret_cast<const uint32_t*>(buf + OAH + ra);
                ah[i][1] = *reinterpret_cast<const uint32_t*>(buf + OAH + ra + 8 * SA);
                ah[i][2] = *reinterpret_cast<const uint32_t*>(buf + OAH + ra + 8);
                ah[i][3] = *reinterpret_cast<const uint32_t*>(buf + OAH + ra + 8 * SA + 8);
                al[i][0] = *reinterpret_cast<const uint32_t*>(buf + OAL + ra);
                al[i][1] = *reinterpret_cast<const uint32_t*>(buf + OAL + ra + 8 * SA);
                al[i][2] = *reinterpret_cast<const uint32_t*>(buf + OAL + ra + 8);
                al[i][3] = *reinterpret_cast<const uint32_t*>(buf + OAL + ra + 8 * SA + 8);
            }
            #pragma unroll
            for (int j = 0; j < 4; j++) {
                int n = warp_n * 32 + j * 8 + g;
                int rb = (ks + 2 * tg) * SB + n;
                uint32_t h0 = bs[OBH + rb];
                uint32_t h1 = bs[OBH + rb + SB];
                uint32_t h2 = bs[OBH + rb + 8 * SB];
                uint32_t h3 = bs[OBH + rb + 9 * SB];
                bh[j][0] = h0 | (h1 << 16);
                bh[j][1] = h2 | (h3 << 16);
                uint32_t l0 = bs[OBL + rb];
                uint32_t l1 = bs[OBL + rb + SB];
                uint32_t l2 = bs[OBL + rb + 8 * SB];
                uint32_t l3 = bs[OBL + rb + 9 * SB];
                bl[j][0] = l0 | (l1 << 16);
                bl[j][1] = l2 | (l3 << 16);
            }
            #pragma unroll
            for (int i = 0; i < 4; i++)
                #pragma unroll
                for (int j = 0; j < 4; j++) {
                    mma16816(acc[i][j], ah[i], bh[j]);
                    mma16816(acc[i][j], ah[i], bl[j]);
                    mma16816(acc[i][j], al[i], bh[j]);
                }
        }
        __syncthreads();
    }

    // ---- epilogue: + bias, store fp32 ----
    #pragma unroll
    for (int i = 0; i < 4; i++) {
        #pragma unroll
        for (int j = 0; j < 4; j++) {
            int row0 = by * 128 + warp_m * 64 + i * 16 + g;
            int col  = bx * 128 + warp_n * 32 + j * 8 + tg * 2;
            float b0 = bias[col], b1 = bias[col + 1];
            float2 v0 = make_float2(acc[i][j][0] + b0, acc[i][j][1] + b1);
            float2 v1 = make_float2(acc[i][j][2] + b0, acc[i][j][3] + b1);
            *reinterpret_cast<float2*>(C + (size_t)row0 * N + col) = v0;
            *reinterpret_cast<float2*>(C + (size_t)(row0 + 8) * N + col) = v1;
        }
    }
}

// ---------------- RoPE + scatter to head-major Q/K/V ----------------
__global__ __launch_bounds__(128) void qkv_rope_kernel(
    const float* __restrict__ mixed,
    float* __restrict__ Q, float* __restrict__ K, float* __restrict__ V)
{
    const int t = blockIdx.x;
    const int h = blockIdx.y;
    const int d = threadIdx.x;

    const float* base = mixed + (size_t)t * NQKV + h * (3 * HD);
    float q = base[d];
    float k = base[HD + d];
    float v = base[2 * HD + d];

    if (d < ROT) {
        const int i = d & 15;
        float inv_freq = 1.0f / powf(10000.0f, (float)(2 * i) * (1.0f / (float)ROT));
        float ang = (float)t * inv_freq;
        float s, c;
        sincosf(ang, &s, &c);
        if (d < 16) {
            q = q * c - base[d + 16] * s;
            k = k * c - base[HD + d + 16] * s;
        } else {
            q = q * c + base[d - 16] * s;
            k = k * c + base[HD + d - 16] * s;
        }
    }

    size_t off = ((size_t)h * S_LEN + t) * HD + d;
    Q[off] = q;
    K[off] = k;
    V[off] = v;
}

// ---------------- flash attention (fp32, causal) ----------------
#define FM 64
#define FN 64
#define KST_LD 65
#define FLASH_SMEM ((FM*HD + HD*KST_LD + FN*HD + FM*FN) * 4)

__global__ __launch_bounds__(256) void flash_attn_kernel(
    const float* __restrict__ Q, const float* __restrict__ K,
    const float* __restrict__ V, float* __restrict__ ctx)
{
    extern __shared__ float smem[];
    float* Qs  = smem;
    float* Kst = Qs  + FM * HD;
    float* Vs  = Kst + HD * KST_LD;
    float* Ps  = Vs  + FN * HD;

    const int h   = blockIdx.y;
    const int m0  = blockIdx.x * FM;
    const int tid = threadIdx.x;
    const int tr  = tid >> 4;
    const int tc  = tid & 15;

    const float* Qh = Q + ((size_t)h * S_LEN + m0) * HD;
    const float* Kh = K + (size_t)h * S_LEN * HD;
    const float* Vh = V + (size_t)h * S_LEN * HD;

    for (int idx = tid; idx < FM * HD / 4; idx += 256) {
        int r = idx >> 5;
        int c = (idx & 31) << 2;
        *reinterpret_cast<float4*>(Qs + r * HD + c) =
            *reinterpret_cast<const float4*>(Qh + (size_t)r * HD + c);
    }

    float m_i[4], l_i[4], o[4][8];
    #pragma unroll
    for (int i = 0; i < 4; i++) {
        m_i[i] = -1e30f;
        l_i[i] = 0.0f;
        #pragma unroll
        for (int x = 0; x < 8; x++) o[i][x] = 0.0f;
    }

    const float scale = 0.08838834764831845f;

    for (int n0 = 0; n0 <= m0; n0 += FN) {
        __syncthreads();

        for (int idx = tid; idx < FN * HD; idx += 256) {
            int r = idx >> 7;
            int c = idx & 127;
            Kst[c * KST_LD + r] = Kh[(size_t)(n0 + r) * HD + c];
        }
        for (int idx = tid; idx < FN * HD / 4; idx += 256) {
            int r = idx >> 5;
            int c = (idx & 31) << 2;
            *reinterpret_cast<float4*>(Vs + r * HD + c) =
                *reinterpret_cast<const float4*>(Vh + (size_t)(n0 + r) * HD + c);
        }
        __syncthreads();

        float s[4][4];
        #pragma unroll
        for (int i = 0; i < 4; i++)
            #pragma unroll
            for (int j = 0; j < 4; j++) s[i][j] = 0.0f;

        #pragma unroll 4
        for (int k = 0; k < HD; k++) {
            float qa[4], kb[4];
            #pragma unroll
            for (int i = 0; i < 4; i++) qa[i] = Qs[(tr * 4 + i) * HD + k];
            #pragma unroll
            for (int j = 0; j < 4; j++) kb[j] = Kst[k * KST_LD + tc + 16 * j];
            #pragma unroll
            for (int i = 0; i < 4; i++)
                #pragma unroll
                for (int j = 0; j < 4; j++) s[i][j] += qa[i] * kb[j];
        }

        #pragma unroll
        for (int i = 0; i < 4; i++) {
            int row = m0 + tr * 4 + i;
            #pragma unroll
            for (int j = 0; j < 4; j++) {
                int key = n0 + tc + 16 * j;
                s[i][j] = (key > row) ? -1e30f : s[i][j] * scale;
            }
        }

        #pragma unroll
        for (int i = 0; i < 4; i++) {
            float mx = fmaxf(fmaxf(s[i][0], s[i][1]), fmaxf(s[i][2], s[i][3]));
            #pragma unroll
            for (int off = 8; off > 0; off >>= 1)
                mx = fmaxf(mx, __shfl_xor_sync(0xffffffffu, mx, off, 16));
            float m_new = fmaxf(m_i[i], mx);
            float alpha = __expf(m_i[i] - m_new);
            m_i[i] = m_new;

            float rs = 0.0f;
            #pragma unroll
            for (int j = 0; j < 4; j++) {
                float p = __expf(s[i][j] - m_new);
                s[i][j] = p;
                rs += p;
            }
            #pragma unroll
            for (int off = 8; off > 0; off >>= 1)
                rs += __shfl_xor_sync(0xffffffffu, rs, off, 16);

            l_i[i] = l_i[i] * alpha + rs;
            #pragma unroll
            for (int x = 0; x < 8; x++) o[i][x] *= alpha;
            #pragma unroll
            for (int j = 0; j < 4; j++)
                Ps[(tr * 4 + i) * FN + tc + 16 * j] = s[i][j];
        }
        __syncthreads();

        #pragma unroll 2
        for (int jj = 0; jj < FN; jj++) {
            float pv[4];
            #pragma unroll
            for (int i = 0; i < 4; i++) pv[i] = Ps[(tr * 4 + i) * FN + jj];
            float4 v0 = *reinterpret_cast<float4*>(Vs + jj * HD + tc * 8);
            float4 v1 = *reinterpret_cast<float4*>(Vs + jj * HD + tc * 8 + 4);
            #pragma unroll
            for (int i = 0; i < 4; i++) {
                o[i][0] += pv[i] * v0.x;  o[i][1] += pv[i] * v0.y;
                o[i][2] += pv[i] * v0.z;  o[i][3] += pv[i] * v0.w;
                o[i][4] += pv[i] * v1.x;  o[i][5] += pv[i] * v1.y;
                o[i][6] += pv[i] * v1.z;  o[i][7] += pv[i] * v1.w;
            }
        }
    }

    #pragma unroll
    for (int i = 0; i < 4; i++) {
        int row = m0 + tr * 4 + i;
        float inv = 1.0f / l_i[i];
        float4 r0, r1;
        r0.x = o[i][0] * inv;  r0.y = o[i][1] * inv;
        r0.z = o[i][2] * inv;  r0.w = o[i][3] * inv;
        r1.x = o[i][4] * inv;  r1.y = o[i][5] * inv;
        r1.z = o[i][6] * inv;  r1.w = o[i][7] * inv;
        float* dst = ctx + (size_t)row * HID + h * HD + tc * 8;
        *reinterpret_cast<float4*>(dst)     = r0;
        *reinterpret_cast<float4*>(dst + 4) = r1;
    }
}

// ---------------- launch ----------------
extern "C" void kernel_launch(void* const* d_in, const int* in_sizes, int n_in,
                              void* d_out, int out_size)
{
    const float* hidden  = (const float*)d_in[0];
    const float* W_qkv   = (const float*)d_in[1];
    const float* b_qkv   = (const float*)d_in[2];
    const float* W_dense = (const float*)d_in[3];
    const float* b_dense = (const float*)d_in[4];
    float* out = (float*)d_out;

    float *mixed, *q, *k, *v, *ctx;
    bf16 *ah, *al, *bh, *bl, *wh, *wl, *ch, *cl;
    cudaGetSymbolAddress((void**)&mixed, g_mixed);
    cudaGetSymbolAddress((void**)&q,     g_q);
    cudaGetSymbolAddress((void**)&k,     g_k);
    cudaGetSymbolAddress((void**)&v,     g_v);
    cudaGetSymbolAddress((void**)&ctx,   g_ctx);
    cudaGetSymbolAddress((void**)&ah,    g_ah);
    cudaGetSymbolAddress((void**)&al,    g_al);
    cudaGetSymbolAddress((void**)&bh,    g_bh);
    cudaGetSymbolAddress((void**)&bl,    g_bl);
    cudaGetSymbolAddress((void**)&wh,    g_wh);
    cudaGetSymbolAddress((void**)&wl,    g_wl);
    cudaGetSymbolAddress((void**)&ch,    g_ch);
    cudaGetSymbolAddress((void**)&cl,    g_cl);

    cudaFuncSetAttribute(flash_attn_kernel,
                         cudaFuncAttributeMaxDynamicSharedMemorySize, FLASH_SMEM);
    cudaFuncSetAttribute(mma_gemm_bf16x3,
                         cudaFuncAttributeMaxDynamicSharedMemorySize, GEMM_SMEM);

    // 0) bf16 hi/lo splits of inputs
    {
        int n4 = S_LEN * HID / 4;
        split_bf16_kernel<<<(n4 + 255) / 256, 256>>>(hidden, ah, al, n4);
        int w4 = HID * NQKV / 4;
        split_bf16_kernel<<<(w4 + 255) / 256, 256>>>(W_qkv, bh, bl, w4);
        int d4 = HID * HID / 4;
        split_bf16_kernel<<<(d4 + 255) / 256, 256>>>(W_dense, wh, wl, d4);
    }

    // 1) QKV projection (+bias), tensor cores
    {
        dim3 grid(NQKV / 128, S_LEN / 128);
        mma_gemm_bf16x3<<<grid, 256, GEMM_SMEM>>>(ah, al, bh, bl, b_qkv, mixed,
                                                  S_LEN, NQKV, HID);
    }

    // 2) RoPE + scatter
    qkv_rope_kernel<<<dim3(S_LEN, NH), 128>>>(mixed, q, k, v);

    // 3) causal flash attention (fp32)
    flash_attn_kernel<<<dim3(S_LEN / FM, NH), 256, FLASH_SMEM>>>(q, k, v, ctx);

    // 4) split ctx, dense projection (+bias), tensor cores
    {
        int c4 = S_LEN * HID / 4;
        split_bf16_kernel<<<(c4 + 255) / 256, 256>>>(ctx, ch, cl, c4);
        dim3 grid(HID / 128, S_LEN / 128);
        mma_gemm_bf16x3<<<grid, 256, GEMM_SMEM>>>(ch, cl, wh, wl, b_dense, out,
                                                  S_LEN, HID, HID);
    }
}

// round 4
// speedup vs baseline: 2.4694x; 1.6006x over previous
#include <cuda_runtime.h>
#include <cuda_bf16.h>
#include <cstdint>
#include <math.h>

using std::uint32_t;

// ---------------- problem constants ----------------
#define S_LEN 2048
#define HID   2048
#define NH    16
#define HD    128
#define NQKV  6144   // 3 * HID
#define ROT   32

typedef __nv_bfloat16 bf16;

// ---------------- scratch (device globals; no runtime alloc) ----------------
__device__ float g_mixed[(size_t)S_LEN * NQKV];        // 48 MB
__device__ float g_ctx[(size_t)S_LEN * HID];           // 16 MB

// bf16 hi/lo splits
__device__ bf16 g_ah[(size_t)S_LEN * HID];             // hidden hi
__device__ bf16 g_al[(size_t)S_LEN * HID];             // hidden lo
__device__ bf16 g_bh[(size_t)HID * NQKV];              // W_qkv hi
__device__ bf16 g_bl[(size_t)HID * NQKV];              // W_qkv lo
__device__ bf16 g_wh[(size_t)HID * HID];               // W_dense hi
__device__ bf16 g_wl[(size_t)HID * HID];               // W_dense lo
__device__ bf16 g_ch[(size_t)S_LEN * HID];             // ctx hi
__device__ bf16 g_cl[(size_t)S_LEN * HID];             // ctx lo

// q/k/v head-major bf16 hi/lo (written by rope kernel)
__device__ bf16 g_qh[(size_t)NH * S_LEN * HD];
__device__ bf16 g_ql[(size_t)NH * S_LEN * HD];
__device__ bf16 g_kh[(size_t)NH * S_LEN * HD];
__device__ bf16 g_kl[(size_t)NH * S_LEN * HD];
__device__ bf16 g_vh[(size_t)NH * S_LEN * HD];
__device__ bf16 g_vl[(size_t)NH * S_LEN * HD];

// ---------------- common PTX helpers ----------------
__device__ __forceinline__ void cp_async16(void* smem_dst, const void* gmem_src) {
    uint32_t s = (uint32_t)__cvta_generic_to_shared(smem_dst);
    asm volatile("cp.async.cg.shared.global [%0], [%1], 16;\n" :: "r"(s), "l"(gmem_src));
}
__device__ __forceinline__ void cp_commit() {
    asm volatile("cp.async.commit_group;\n");
}
template <int N>
__device__ __forceinline__ void cp_wait() {
    asm volatile("cp.async.wait_group %0;\n" :: "n"(N));
}

__device__ __forceinline__ void mma16816(float* c, const uint32_t* a, const uint32_t* b) {
    asm volatile(
        "mma.sync.aligned.m16n8k16.row.col.f32.bf16.bf16.f32 "
        "{%0,%1,%2,%3}, {%4,%5,%6,%7}, {%8,%9}, {%0,%1,%2,%3};\n"
        : "+f"(c[0]), "+f"(c[1]), "+f"(c[2]), "+f"(c[3])
        : "r"(a[0]), "r"(a[1]), "r"(a[2]), "r"(a[3]), "r"(b[0]), "r"(b[1]));
}

__device__ __forceinline__ void ldmx4(uint32_t* r, const void* p) {
    uint32_t a = (uint32_t)__cvta_generic_to_shared(p);
    asm volatile("ldmatrix.sync.aligned.m8n8.x4.shared.b16 {%0,%1,%2,%3}, [%4];"
                 : "=r"(r[0]), "=r"(r[1]), "=r"(r[2]), "=r"(r[3]) : "r"(a));
}
__device__ __forceinline__ void ldmx4t(uint32_t* r, const void* p) {
    uint32_t a = (uint32_t)__cvta_generic_to_shared(p);
    asm volatile("ldmatrix.sync.aligned.m8n8.x4.trans.shared.b16 {%0,%1,%2,%3}, [%4];"
                 : "=r"(r[0]), "=r"(r[1]), "=r"(r[2]), "=r"(r[3]) : "r"(a));
}

// ---------------- fp32 -> bf16 hi/lo split ----------------
__global__ __launch_bounds__(256) void split_bf16_kernel(
    const float* __restrict__ x, bf16* __restrict__ hi, bf16* __restrict__ lo, int n4)
{
    int i = blockIdx.x * blockDim.x + threadIdx.x;
    if (i >= n4) return;
    float4 v = reinterpret_cast<const float4*>(x)[i];
    bf16 h0 = __float2bfloat16(v.x);
    bf16 h1 = __float2bfloat16(v.y);
    bf16 h2 = __float2bfloat16(v.z);
    bf16 h3 = __float2bfloat16(v.w);
    bf16 l0 = __float2bfloat16(v.x - __bfloat162float(h0));
    bf16 l1 = __float2bfloat16(v.y - __bfloat162float(h1));
    bf16 l2 = __float2bfloat16(v.z - __bfloat162float(h2));
    bf16 l3 = __float2bfloat16(v.w - __bfloat162float(h3));
    __nv_bfloat162* hp = reinterpret_cast<__nv_bfloat162*>(hi);
    __nv_bfloat162* lp = reinterpret_cast<__nv_bfloat162*>(lo);
    hp[2 * i]     = __nv_bfloat162(h0, h1);
    hp[2 * i + 1] = __nv_bfloat162(h2, h3);
    lp[2 * i]     = __nv_bfloat162(l0, l1);
    lp[2 * i + 1] = __nv_bfloat162(l2, l3);
}

// ---------------- tensor-core GEMM (bf16x3, fp32 accum) ----------------
#define GBK 32
#define SA     40
#define SB     136
#define OAH    0
#define OAL    (128 * SA)
#define OBH    (2 * 128 * SA)
#define OBL    (OBH + 32 * SB)
#define BUFSZ  (OBL + 32 * SB)
#define GEMM_SMEM (2 * BUFSZ * 2)

__global__ __launch_bounds__(256, 1) void mma_gemm_bf16x3(
    const bf16* __restrict__ Ah, const bf16* __restrict__ Al,
    const bf16* __restrict__ Bh, const bf16* __restrict__ Bl,
    const float* __restrict__ bias, float* __restrict__ C,
    int M, int N, int K)
{
    extern __shared__ __align__(16) unsigned char smraw[];
    bf16* sm = reinterpret_cast<bf16*>(smraw);

    const int bx = blockIdx.x;
    const int by = blockIdx.y;
    const int tid = threadIdx.x;
    const int warp = tid >> 5;
    const int lane = tid & 31;
    const int warp_m = warp >> 2;      // 0..1
    const int warp_n = warp & 3;       // 0..3
    const int g  = lane >> 2;
    const int tg = lane & 3;

    const int nstage = K / GBK;

    float acc[4][4][4];
    #pragma unroll
    for (int i = 0; i < 4; i++)
        #pragma unroll
        for (int j = 0; j < 4; j++)
            #pragma unroll
            for (int x = 0; x < 4; x++) acc[i][j][x] = 0.0f;

    auto issue = [&](int s) {
        const int k0 = s * GBK;
        bf16* buf = sm + (s & 1) * BUFSZ;
        #pragma unroll
        for (int q = tid; q < 512; q += 256) {
            int r = q >> 2, c = q & 3;
            size_t goff = (size_t)(by * 128 + r) * K + k0 + c * 8;
            int soff = r * SA + c * 8;
            cp_async16(buf + OAH + soff, Ah + goff);
            cp_async16(buf + OAL + soff, Al + goff);
        }
        #pragma unroll
        for (int q = tid; q < 512; q += 256) {
            int kr = q >> 4, c = q & 15;
            size_t goff = (size_t)(k0 + kr) * N + bx * 128 + c * 8;
            int soff = kr * SB + c * 8;
            cp_async16(buf + OBH + soff, Bh + goff);
            cp_async16(buf + OBL + soff, Bl + goff);
        }
    };

    issue(0);
    cp_commit();

    // ldmatrix lane-address components
    const int a_row = lane & 15;             // row within m16 tile
    const int a_colh = (lane >> 4) << 3;     // 0 or 8 (k half)
    const int b_row = lane & 15;             // k row within k16
    const int b_colh = (lane >> 4) << 3;     // 0 or 8 (n half)

    for (int s = 0; s < nstage; s++) {
        if (s + 1 < nstage) {
            issue(s + 1);
            cp_commit();
            cp_wait<1>();
        } else {
            cp_wait<0>();
        }
        __syncthreads();

        const bf16* buf = sm + (s & 1) * BUFSZ;

        #pragma unroll
        for (int ks = 0; ks < GBK; ks += 16) {
            uint32_t ah[4][4], al[4][4], bh[4][2], bl[4][2];
            #pragma unroll
            for (int i = 0; i < 4; i++) {
                int ra = (warp_m * 64 + i * 16 + a_row) * SA + ks + a_colh;
                ldmx4(ah[i], buf + OAH + ra);
                ldmx4(al[i], buf + OAL + ra);
            }
            #pragma unroll
            for (int jp = 0; jp < 2; jp++) {
                int rb = (ks + b_row) * SB + warp_n * 32 + jp * 16 + b_colh;
                uint32_t th[4], tl[4];
                ldmx4t(th, buf + OBH + rb);
                ldmx4t(tl, buf + OBL + rb);
                bh[2 * jp][0] = th[0]; bh[2 * jp][1] = th[1];
                bh[2 * jp + 1][0] = th[2]; bh[2 * jp + 1][1] = th[3];
                bl[2 * jp][0] = tl[0]; bl[2 * jp][1] = tl[1];
                bl[2 * jp + 1][0] = tl[2]; bl[2 * jp + 1][1] = tl[3];
            }
            #pragma unroll
            for (int i = 0; i < 4; i++)
                #pragma unroll
                for (int j = 0; j < 4; j++) {
                    mma16816(acc[i][j], ah[i], bh[j]);
                    mma16816(acc[i][j], ah[i], bl[j]);
                    mma16816(acc[i][j], al[i], bh[j]);
                }
        }
        __syncthreads();
    }

    #pragma unroll
    for (int i = 0; i < 4; i++) {
        #pragma unroll
        for (int j = 0; j < 4; j++) {
            int row0 = by * 128 + warp_m * 64 + i * 16 + g;
            int col  = bx * 128 + warp_n * 32 + j * 8 + tg * 2;
            float b0 = bias[col], b1 = bias[col + 1];
            float2 v0 = make_float2(acc[i][j][0] + b0, acc[i][j][1] + b1);
            float2 v1 = make_float2(acc[i][j][2] + b0, acc[i][j][3] + b1);
            *reinterpret_cast<float2*>(C + (size_t)row0 * N + col) = v0;
            *reinterpret_cast<float2*>(C + (size_t)(row0 + 8) * N + col) = v1;
        }
    }
}

// ---------------- RoPE + scatter + bf16 hi/lo split ----------------
__global__ __launch_bounds__(128) void qkv_rope_split_kernel(
    const float* __restrict__ mixed,
    bf16* __restrict__ Qh, bf16* __restrict__ Ql,
    bf16* __restrict__ Kh, bf16* __restrict__ Kl,
    bf16* __restrict__ Vh, bf16* __restrict__ Vl)
{
    const int t = blockIdx.x;
    const int h = blockIdx.y;
    const int d = threadIdx.x;

    const float* base = mixed + (size_t)t * NQKV + h * (3 * HD);
    float q = base[d];
    float k = base[HD + d];
    float v = base[2 * HD + d];

    if (d < ROT) {
        const int i = d & 15;
        float inv_freq = 1.0f / powf(10000.0f, (float)(2 * i) * (1.0f / (float)ROT));
        float ang = (float)t * inv_freq;
        float s, c;
        sincosf(ang, &s, &c);
        if (d < 16) {
            q = q * c - base[d + 16] * s;
            k = k * c - base[HD + d + 16] * s;
        } else {
            q = q * c + base[d - 16] * s;
            k = k * c + base[HD + d - 16] * s;
        }
    }

    size_t off = ((size_t)h * S_LEN + t) * HD + d;
    bf16 qhi = __float2bfloat16(q);
    bf16 khi = __float2bfloat16(k);
    bf16 vhi = __float2bfloat16(v);
    Qh[off] = qhi;  Ql[off] = __float2bfloat16(q - __bfloat162float(qhi));
    Kh[off] = khi;  Kl[off] = __float2bfloat16(k - __bfloat162float(khi));
    Vh[off] = vhi;  Vl[off] = __float2bfloat16(v - __bfloat162float(vhi));
}

// ---------------- tensor-core flash attention (bf16x3, causal) ----------------
// BM=128, BN=64, 256 threads (8 warps), warp owns 16 query rows.
#define FBM 128
#define FBN 64
#define FSTR 136   // padded row stride (bf16 elems)

// smem element offsets
#define FQH 0
#define FQL (128 * FSTR)
#define FKH (2 * 128 * FSTR)
#define FKL (FKH + 64 * FSTR)
#define FVH (FKL + 64 * FSTR)
#define FVL (FVH + 64 * FSTR)
#define FLASH_SMEM ((FVL + 64 * FSTR) * 2)   // bytes

__global__ __launch_bounds__(256, 1) void flash_mma_kernel(
    const bf16* __restrict__ Qh, const bf16* __restrict__ Ql,
    const bf16* __restrict__ Kh, const bf16* __restrict__ Kl,
    const bf16* __restrict__ Vh, const bf16* __restrict__ Vl,
    float* __restrict__ ctx)
{
    extern __shared__ __align__(16) unsigned char fsraw[];
    bf16* fs = reinterpret_cast<bf16*>(fsraw);

    const int h = blockIdx.y;
    const int m_tile = gridDim.x - 1 - blockIdx.x;   // long blocks first
    const int m0 = m_tile * FBM;
    const int tid = threadIdx.x;
    const int warp = tid >> 5;
    const int lane = tid & 31;
    const int g  = lane >> 2;
    const int tg = lane & 3;

    const bf16* qhp = Qh + ((size_t)h * S_LEN + m0) * HD;
    const bf16* qlp = Ql + ((size_t)h * S_LEN + m0) * HD;
    const bf16* khp = Kh + (size_t)h * S_LEN * HD;
    const bf16* klp = Kl + (size_t)h * S_LEN * HD;
    const bf16* vhp = Vh + (size_t)h * S_LEN * HD;
    const bf16* vlp = Vl + (size_t)h * S_LEN * HD;

    // load Q tile (128 rows x 16 float4 chunks)
    for (int idx = tid; idx < 2048; idx += 256) {
        int r = idx >> 4, c = (idx & 15) << 3;
        *reinterpret_cast<float4*>(fs + FQH + r * FSTR + c) =
            *reinterpret_cast<const float4*>(qhp + (size_t)r * HD + c);
        *reinterpret_cast<float4*>(fs + FQL + r * FSTR + c) =
            *reinterpret_cast<const float4*>(qlp + (size_t)r * HD + c);
    }

    float o[16][4];
    #pragma unroll
    for (int j = 0; j < 16; j++)
        #pragma unroll
        for (int x = 0; x < 4; x++) o[j][x] = 0.0f;
    float mrow0 = -1e30f, mrow1 = -1e30f, lrow0 = 0.0f, lrow1 = 0.0f;

    const float scale = 0.08838834764831845f;   // 1/sqrt(128)
    const int row0 = m0 + warp * 16 + g;
    const int row1 = row0 + 8;
    const int wrow_max = m0 + warp * 16 + 15;

    const int a_row = lane & 15;
    const int half8 = (lane >> 4) << 3;          // 0 or 8
    const int bk_colh = ((lane >> 3) & 1) << 3;  // 0 or 8

    const int ntiles = m0 / FBN + 2;
    for (int nt = 0; nt < ntiles; nt++) {
        const int n0 = nt * FBN;
        __syncthreads();
        // load K/V tiles (64 rows x 16 chunks each)
        for (int idx = tid; idx < 1024; idx += 256) {
            int r = idx >> 4, c = (idx & 15) << 3;
            size_t go = (size_t)(n0 + r) * HD + c;
            int so = r * FSTR + c;
            *reinterpret_cast<float4*>(fs + FKH + so) = *reinterpret_cast<const float4*>(khp + go);
            *reinterpret_cast<float4*>(fs + FKL + so) = *reinterpret_cast<const float4*>(klp + go);
            *reinterpret_cast<float4*>(fs + FVH + so) = *reinterpret_cast<const float4*>(vhp + go);
            *reinterpret_cast<float4*>(fs + FVL + so) = *reinterpret_cast<const float4*>(vlp + go);
        }
        __syncthreads();

        if (n0 > wrow_max) continue;   // fully masked for this warp

        // ---- S = Q K^T (bf16x3) ----
        float sacc[8][4];
        #pragma unroll
        for (int j = 0; j < 8; j++)
            #pragma unroll
            for (int x = 0; x < 4; x++) sacc[j][x] = 0.0f;

        #pragma unroll
        for (int ks = 0; ks < 8; ks++) {
            const int k = ks * 16;
            uint32_t aH[4], aL[4];
            {
                int ra = (warp * 16 + a_row) * FSTR + k + half8;
                ldmx4(aH, fs + FQH + ra);
                ldmx4(aL, fs + FQL + ra);
            }
            #pragma unroll
            for (int jp = 0; jp < 4; jp++) {
                // K b-frags: non-trans ldmatrix, rows = key n, cols = k
                int rb = (jp * 16 + half8 + (lane & 7)) * FSTR + k + bk_colh;
                uint32_t bH[4], bL[4];
                ldmx4(bH, fs + FKH + rb);
                ldmx4(bL, fs + FKL + rb);
                uint32_t b0h[2] = {bH[0], bH[1]}, b1h[2] = {bH[2], bH[3]};
                uint32_t b0l[2] = {bL[0], bL[1]}, b1l[2] = {bL[2], bL[3]};
                mma16816(sacc[2 * jp],     aH, b0h);
                mma16816(sacc[2 * jp],     aH, b0l);
                mma16816(sacc[2 * jp],     aL, b0h);
                mma16816(sacc[2 * jp + 1], aH, b1h);
                mma16816(sacc[2 * jp + 1], aH, b1l);
                mma16816(sacc[2 * jp + 1], aL, b1h);
            }
        }

        // ---- scale + causal mask ----
        const bool boundary = (n0 + FBN - 1 > m0);
        #pragma unroll
        for (int j = 0; j < 8; j++) {
            int c0 = n0 + j * 8 + 2 * tg;
            if (boundary) {
                sacc[j][0] = (c0     > row0) ? -1e30f : sacc[j][0] * scale;
                sacc[j][1] = (c0 + 1 > row0) ? -1e30f : sacc[j][1] * scale;
                sacc[j][2] = (c0     > row1) ? -1e30f : sacc[j][2] * scale;
                sacc[j][3] = (c0 + 1 > row1) ? -1e30f : sacc[j][3] * scale;
            } else {
                sacc[j][0] *= scale; sacc[j][1] *= scale;
                sacc[j][2] *= scale; sacc[j][3] *= scale;
            }
        }

        // ---- online softmax ----
        float mx0 = -1e30f, mx1 = -1e30f;
        #pragma unroll
        for (int j = 0; j < 8; j++) {
            mx0 = fmaxf(mx0, fmaxf(sacc[j][0], sacc[j][1]));
            mx1 = fmaxf(mx1, fmaxf(sacc[j][2], sacc[j][3]));
        }
        mx0 = fmaxf(mx0, __shfl_xor_sync(0xffffffffu, mx0, 1));
        mx0 = fmaxf(mx0, __shfl_xor_sync(0xffffffffu, mx0, 2));
        mx1 = fmaxf(mx1, __shfl_xor_sync(0xffffffffu, mx1, 1));
        mx1 = fmaxf(mx1, __shfl_xor_sync(0xffffffffu, mx1, 2));

        float mn0 = fmaxf(mrow0, mx0);
        float mn1 = fmaxf(mrow1, mx1);
        float alpha0 = __expf(mrow0 - mn0);
        float alpha1 = __expf(mrow1 - mn1);
        mrow0 = mn0; mrow1 = mn1;

        float sum0 = 0.0f, sum1 = 0.0f;
        #pragma unroll
        for (int j = 0; j < 8; j++) {
            sacc[j][0] = __expf(sacc[j][0] - mn0);
            sacc[j][1] = __expf(sacc[j][1] - mn0);
            sacc[j][2] = __expf(sacc[j][2] - mn1);
            sacc[j][3] = __expf(sacc[j][3] - mn1);
            sum0 += sacc[j][0] + sacc[j][1];
            sum1 += sacc[j][2] + sacc[j][3];
        }
        sum0 += __shfl_xor_sync(0xffffffffu, sum0, 1);
        sum0 += __shfl_xor_sync(0xffffffffu, sum0, 2);
        sum1 += __shfl_xor_sync(0xffffffffu, sum1, 1);
        sum1 += __shfl_xor_sync(0xffffffffu, sum1, 2);
        lrow0 = lrow0 * alpha0 + sum0;
        lrow1 = lrow1 * alpha1 + sum1;

        #pragma unroll
        for (int j = 0; j < 16; j++) {
            o[j][0] *= alpha0; o[j][1] *= alpha0;
            o[j][2] *= alpha1; o[j][3] *= alpha1;
        }

        // ---- O += P V (bf16x3), P a-frags straight from registers ----
        #pragma unroll
        for (int kk = 0; kk < 4; kk++) {
            uint32_t paH[4], paL[4];
            #pragma unroll
            for (int half = 0; half < 2; half++) {     // k-half: ntile 2kk / 2kk+1
                const float* sv = sacc[2 * kk + half];
                __nv_bfloat162 h0 = __floats2bfloat162_rn(sv[0], sv[1]);
                __nv_bfloat162 h1 = __floats2bfloat162_rn(sv[2], sv[3]);
                __nv_bfloat162 l0 = __floats2bfloat162_rn(
                    sv[0] - __bfloat162float(h0.x), sv[1] - __bfloat162float(h0.y));
                __nv_bfloat162 l1 = __floats2bfloat162_rn(
                    sv[2] - __bfloat162float(h1.x), sv[3] - __bfloat162float(h1.y));
                paH[2 * half]     = *reinterpret_cast<uint32_t*>(&h0);
                paH[2 * half + 1] = *reinterpret_cast<uint32_t*>(&h1);
                paL[2 * half]     = *reinterpret_cast<uint32_t*>(&l0);
                paL[2 * half + 1] = *reinterpret_cast<uint32_t*>(&l1);
            }
            #pragma unroll
            for (int jp = 0; jp < 8; jp++) {
                int rv = (kk * 16 + a_row) * FSTR + jp * 16 + half8;
                uint32_t vH[4], vL[4];
                ldmx4t(vH, fs + FVH + rv);
                ldmx4t(vL, fs + FVL + rv);
                uint32_t v0h[2] = {vH[0], vH[1]}, v1h[2] = {vH[2], vH[3]};
                uint32_t v0l[2] = {vL[0], vL[1]}, v1l[2] = {vL[2], vL[3]};
                mma16816(o[2 * jp],     paH, v0h);
                mma16816(o[2 * jp],     paH, v0l);
                mma16816(o[2 * jp],     paL, v0h);
                mma16816(o[2 * jp + 1], paH, v1h);
                mma16816(o[2 * jp + 1], paH, v1l);
                mma16816(o[2 * jp + 1], paL, v1h);
            }
        }
    }

    // ---- epilogue: O /= l, write ctx[s, h*128 + d] fp32 ----
    float inv0 = 1.0f / lrow0;
    float inv1 = 1.0f / lrow1;
    #pragma unroll
    for (int jt = 0; jt < 16; jt++) {
        int col = h * HD + jt * 8 + 2 * tg;
        float2 r0 = make_float2(o[jt][0] * inv0, o[jt][1] * inv0);
        float2 r1 = make_float2(o[jt][2] * inv1, o[jt][3] * inv1);
        *reinterpret_cast<float2*>(ctx + (size_t)row0 * HID + col) = r0;
        *reinterpret_cast<float2*>(ctx + (size_t)row1 * HID + col) = r1;
    }
}

// ---------------- launch ----------------
extern "C" void kernel_launch(void* const* d_in, const int* in_sizes, int n_in,
                              void* d_out, int out_size)
{
    const float* hidden  = (const float*)d_in[0];
    const float* W_qkv   = (const float*)d_in[1];
    const float* b_qkv   = (const float*)d_in[2];
    const float* W_dense = (const float*)d_in[3];
    const float* b_dense = (const float*)d_in[4];
    float* out = (float*)d_out;

    float *mixed, *ctx;
    bf16 *ah, *al, *bh, *bl, *wh, *wl, *ch, *cl;
    bf16 *qh, *ql, *kh, *kl, *vh, *vl;
    cudaGetSymbolAddress((void**)&mixed, g_mixed);
    cudaGetSymbolAddress((void**)&ctx,   g_ctx);
    cudaGetSymbolAddress((void**)&ah,    g_ah);
    cudaGetSymbolAddress((void**)&al,    g_al);
    cudaGetSymbolAddress((void**)&bh,    g_bh);
    cudaGetSymbolAddress((void**)&bl,    g_bl);
    cudaGetSymbolAddress((void**)&wh,    g_wh);
    cudaGetSymbolAddress((void**)&wl,    g_wl);
    cudaGetSymbolAddress((void**)&ch,    g_ch);
    cudaGetSymbolAddress((void**)&cl,    g_cl);
    cudaGetSymbolAddress((void**)&qh,    g_qh);
    cudaGetSymbolAddress((void**)&ql,    g_ql);
    cudaGetSymbolAddress((void**)&kh,    g_kh);
    cudaGetSymbolAddress((void**)&kl,    g_kl);
    cudaGetSymbolAddress((void**)&vh,    g_vh);
    cudaGetSymbolAddress((void**)&vl,    g_vl);

    cudaFuncSetAttribute(mma_gemm_bf16x3,
                         cudaFuncAttributeMaxDynamicSharedMemorySize, GEMM_SMEM);
    cudaFuncSetAttribute(flash_mma_kernel,
                         cudaFuncAttributeMaxDynamicSharedMemorySize, FLASH_SMEM);

    // 0) bf16 hi/lo splits of inputs
    {
        int n4 = S_LEN * HID / 4;
        split_bf16_kernel<<<(n4 + 255) / 256, 256>>>(hidden, ah, al, n4);
        int w4 = HID * NQKV / 4;
        split_bf16_kernel<<<(w4 + 255) / 256, 256>>>(W_qkv, bh, bl, w4);
        int d4 = HID * HID / 4;
        split_bf16_kernel<<<(d4 + 255) / 256, 256>>>(W_dense, wh, wl, d4);
    }

    // 1) QKV projection (+bias), tensor cores
    {
        dim3 grid(NQKV / 128, S_LEN / 128);
        mma_gemm_bf16x3<<<grid, 256, GEMM_SMEM>>>(ah, al, bh, bl, b_qkv, mixed,
                                                  S_LEN, NQKV, HID);
    }

    // 2) RoPE + scatter + split
    qkv_rope_split_kernel<<<dim3(S_LEN, NH), 128>>>(mixed, qh, ql, kh, kl, vh, vl);

    // 3) causal flash attention, tensor cores
    flash_mma_kernel<<<dim3(S_LEN / FBM, NH), 256, FLASH_SMEM>>>(
        qh, ql, kh, kl, vh, vl, ctx);

    // 4) split ctx, dense projection (+bias), tensor cores
    {
        int c4 = S_LEN * HID / 4;
        split_bf16_kernel<<<(c4 + 255) / 256, 256>>>(ctx, ch, cl, c4);
        dim3 grid(HID / 128, S_LEN / 128);
        mma_gemm_bf16x3<<<grid, 256, GEMM_SMEM>>>(ch, cl, wh, wl, b_dense, out,
                                                  S_LEN, HID, HID);
    }
}

// round 5
// speedup vs baseline: 2.5204x; 1.0206x over previous
#include <cuda_runtime.h>
#include <cuda_bf16.h>
#include <cstdint>
#include <math.h>

using std::uint32_t;

// ---------------- problem constants ----------------
#define S_LEN 2048
#define HID   2048
#define NH    16
#define HD    128
#define NQKV  6144   // 3 * HID
#define ROT   32

typedef __nv_bfloat16 bf16;

// ---------------- scratch (device globals; no runtime alloc) ----------------
__device__ float g_mixed[(size_t)S_LEN * NQKV];        // 48 MB

// bf16 hi/lo splits
__device__ bf16 g_ah[(size_t)S_LEN * HID];             // hidden hi
__device__ bf16 g_al[(size_t)S_LEN * HID];             // hidden lo
__device__ bf16 g_bh[(size_t)HID * NQKV];              // W_qkv hi
__device__ bf16 g_bl[(size_t)HID * NQKV];              // W_qkv lo
__device__ bf16 g_wh[(size_t)HID * HID];               // W_dense hi
__device__ bf16 g_wl[(size_t)HID * HID];               // W_dense lo
__device__ bf16 g_ch[(size_t)S_LEN * HID];             // ctx hi (written by flash)
__device__ bf16 g_cl[(size_t)S_LEN * HID];             // ctx lo (written by flash)

// q/k/v head-major bf16 hi/lo (written by rope kernel)
__device__ bf16 g_qh[(size_t)NH * S_LEN * HD];
__device__ bf16 g_ql[(size_t)NH * S_LEN * HD];
__device__ bf16 g_kh[(size_t)NH * S_LEN * HD];
__device__ bf16 g_kl[(size_t)NH * S_LEN * HD];
__device__ bf16 g_vh[(size_t)NH * S_LEN * HD];
__device__ bf16 g_vl[(size_t)NH * S_LEN * HD];

// ---------------- common PTX helpers ----------------
__device__ __forceinline__ void cp_async16(void* smem_dst, const void* gmem_src) {
    uint32_t s = (uint32_t)__cvta_generic_to_shared(smem_dst);
    asm volatile("cp.async.cg.shared.global [%0], [%1], 16;\n" :: "r"(s), "l"(gmem_src));
}
__device__ __forceinline__ void cp_commit() {
    asm volatile("cp.async.commit_group;\n");
}
template <int N>
__device__ __forceinline__ void cp_wait() {
    asm volatile("cp.async.wait_group %0;\n" :: "n"(N));
}

__device__ __forceinline__ void mma16816(float* c, const uint32_t* a, const uint32_t* b) {
    asm volatile(
        "mma.sync.aligned.m16n8k16.row.col.f32.bf16.bf16.f32 "
        "{%0,%1,%2,%3}, {%4,%5,%6,%7}, {%8,%9}, {%0,%1,%2,%3};\n"
        : "+f"(c[0]), "+f"(c[1]), "+f"(c[2]), "+f"(c[3])
        : "r"(a[0]), "r"(a[1]), "r"(a[2]), "r"(a[3]), "r"(b[0]), "r"(b[1]));
}

__device__ __forceinline__ void ldmx4(uint32_t* r, const void* p) {
    uint32_t a = (uint32_t)__cvta_generic_to_shared(p);
    asm volatile("ldmatrix.sync.aligned.m8n8.x4.shared.b16 {%0,%1,%2,%3}, [%4];"
                 : "=r"(r[0]), "=r"(r[1]), "=r"(r[2]), "=r"(r[3]) : "r"(a));
}
__device__ __forceinline__ void ldmx4t(uint32_t* r, const void* p) {
    uint32_t a = (uint32_t)__cvta_generic_to_shared(p);
    asm volatile("ldmatrix.sync.aligned.m8n8.x4.trans.shared.b16 {%0,%1,%2,%3}, [%4];"
                 : "=r"(r[0]), "=r"(r[1]), "=r"(r[2]), "=r"(r[3]) : "r"(a));
}

// ---------------- fp32 -> bf16 hi/lo split ----------------
__global__ __launch_bounds__(256) void split_bf16_kernel(
    const float* __restrict__ x, bf16* __restrict__ hi, bf16* __restrict__ lo, int n4)
{
    int i = blockIdx.x * blockDim.x + threadIdx.x;
    if (i >= n4) return;
    float4 v = reinterpret_cast<const float4*>(x)[i];
    bf16 h0 = __float2bfloat16(v.x);
    bf16 h1 = __float2bfloat16(v.y);
    bf16 h2 = __float2bfloat16(v.z);
    bf16 h3 = __float2bfloat16(v.w);
    bf16 l0 = __float2bfloat16(v.x - __bfloat162float(h0));
    bf16 l1 = __float2bfloat16(v.y - __bfloat162float(h1));
    bf16 l2 = __float2bfloat16(v.z - __bfloat162float(h2));
    bf16 l3 = __float2bfloat16(v.w - __bfloat162float(h3));
    __nv_bfloat162* hp = reinterpret_cast<__nv_bfloat162*>(hi);
    __nv_bfloat162* lp = reinterpret_cast<__nv_bfloat162*>(lo);
    hp[2 * i]     = __nv_bfloat162(h0, h1);
    hp[2 * i + 1] = __nv_bfloat162(h2, h3);
    lp[2 * i]     = __nv_bfloat162(l0, l1);
    lp[2 * i + 1] = __nv_bfloat162(l2, l3);
}

// ---------------- tensor-core GEMM (bf16x3, fp32 accum) ----------------
// 128x128 block tile, BK=32, 512 threads (16 warps, 4x4), warp tile 32x32.
// 3-stage cp.async ring, single __syncthreads per stage.
#define GBK 32
#define SA     40
#define SB     136
#define OAH    0
#define OAL    (128 * SA)
#define OBH    (2 * 128 * SA)
#define OBL    (OBH + 32 * SB)
#define BUFSZ  (OBL + 32 * SB)       // 18944 bf16 = 37888 B
#define GEMM_SMEM (3 * BUFSZ * 2)    // 113664 B

__global__ __launch_bounds__(512, 1) void mma_gemm_bf16x3(
    const bf16* __restrict__ Ah, const bf16* __restrict__ Al,
    const bf16* __restrict__ Bh, const bf16* __restrict__ Bl,
    const float* __restrict__ bias, float* __restrict__ C,
    int M, int N, int K)
{
    extern __shared__ __align__(16) unsigned char smraw[];
    bf16* sm = reinterpret_cast<bf16*>(smraw);

    const int bx = blockIdx.x;
    const int by = blockIdx.y;
    const int tid = threadIdx.x;
    const int warp = tid >> 5;
    const int lane = tid & 31;
    const int warp_m = warp >> 2;      // 0..3  (32 rows each)
    const int warp_n = warp & 3;       // 0..3  (32 cols each)
    const int g  = lane >> 2;
    const int tg = lane & 3;

    const int nstage = K / GBK;

    float acc[2][4][4];
    #pragma unroll
    for (int i = 0; i < 2; i++)
        #pragma unroll
        for (int j = 0; j < 4; j++)
            #pragma unroll
            for (int x = 0; x < 4; x++) acc[i][j][x] = 0.0f;

    // per-thread copy mapping (512 threads, 1 chunk each per matrix-half)
    const int arow = tid >> 2, acol = (tid & 3) * 8;        // A: 128x32
    const int brow = tid >> 4, bcol = (tid & 15) * 8;       // B: 32x128

    auto issue = [&](int s) {
        const int k0 = s * GBK;
        bf16* buf = sm + (s % 3) * BUFSZ;
        size_t ga = (size_t)(by * 128 + arow) * K + k0 + acol;
        int sa = arow * SA + acol;
        cp_async16(buf + OAH + sa, Ah + ga);
        cp_async16(buf + OAL + sa, Al + ga);
        size_t gb = (size_t)(k0 + brow) * N + bx * 128 + bcol;
        int sb = brow * SB + bcol;
        cp_async16(buf + OBH + sb, Bh + gb);
        cp_async16(buf + OBL + sb, Bl + gb);
    };

    issue(0); cp_commit();
    issue(1); cp_commit();

    // ldmatrix lane-address components
    const int a_row = lane & 15;
    const int a_colh = (lane >> 4) << 3;
    const int b_row = lane & 15;
    const int b_colh = (lane >> 4) << 3;

    for (int s = 0; s < nstage; s++) {
        cp_wait<1>();
        __syncthreads();
        if (s + 2 < nstage) { issue(s + 2); cp_commit(); }

        const bf16* buf = sm + (s % 3) * BUFSZ;

        #pragma unroll
        for (int ks = 0; ks < GBK; ks += 16) {
            uint32_t ah[2][4], al[2][4], bh[4][2], bl[4][2];
            #pragma unroll
            for (int i = 0; i < 2; i++) {
                int ra = (warp_m * 32 + i * 16 + a_row) * SA + ks + a_colh;
                ldmx4(ah[i], buf + OAH + ra);
                ldmx4(al[i], buf + OAL + ra);
            }
            #pragma unroll
            for (int jp = 0; jp < 2; jp++) {
                int rb = (ks + b_row) * SB + warp_n * 32 + jp * 16 + b_colh;
                uint32_t th[4], tl[4];
                ldmx4t(th, buf + OBH + rb);
                ldmx4t(tl, buf + OBL + rb);
                bh[2 * jp][0] = th[0]; bh[2 * jp][1] = th[1];
                bh[2 * jp + 1][0] = th[2]; bh[2 * jp + 1][1] = th[3];
                bl[2 * jp][0] = tl[0]; bl[2 * jp][1] = tl[1];
                bl[2 * jp + 1][0] = tl[2]; bl[2 * jp + 1][1] = tl[3];
            }
            #pragma unroll
            for (int i = 0; i < 2; i++)
                #pragma unroll
                for (int j = 0; j < 4; j++) {
                    mma16816(acc[i][j], ah[i], bh[j]);
                    mma16816(acc[i][j], ah[i], bl[j]);
                    mma16816(acc[i][j], al[i], bh[j]);
                }
        }
    }

    #pragma unroll
    for (int i = 0; i < 2; i++) {
        #pragma unroll
        for (int j = 0; j < 4; j++) {
            int row0 = by * 128 + warp_m * 32 + i * 16 + g;
            int col  = bx * 128 + warp_n * 32 + j * 8 + tg * 2;
            float b0 = bias[col], b1 = bias[col + 1];
            float2 v0 = make_float2(acc[i][j][0] + b0, acc[i][j][1] + b1);
            float2 v1 = make_float2(acc[i][j][2] + b0, acc[i][j][3] + b1);
            *reinterpret_cast<float2*>(C + (size_t)row0 * N + col) = v0;
            *reinterpret_cast<float2*>(C + (size_t)(row0 + 8) * N + col) = v1;
        }
    }
}

// ---------------- RoPE + scatter + bf16 hi/lo split ----------------
__global__ __launch_bounds__(128) void qkv_rope_split_kernel(
    const float* __restrict__ mixed,
    bf16* __restrict__ Qh, bf16* __restrict__ Ql,
    bf16* __restrict__ Kh, bf16* __restrict__ Kl,
    bf16* __restrict__ Vh, bf16* __restrict__ Vl)
{
    const int t = blockIdx.x;
    const int h = blockIdx.y;
    const int d = threadIdx.x;

    const float* base = mixed + (size_t)t * NQKV + h * (3 * HD);
    float q = base[d];
    float k = base[HD + d];
    float v = base[2 * HD + d];

    if (d < ROT) {
        const int i = d & 15;
        float inv_freq = 1.0f / powf(10000.0f, (float)(2 * i) * (1.0f / (float)ROT));
        float ang = (float)t * inv_freq;
        float s, c;
        sincosf(ang, &s, &c);
        if (d < 16) {
            q = q * c - base[d + 16] * s;
            k = k * c - base[HD + d + 16] * s;
        } else {
            q = q * c + base[d - 16] * s;
            k = k * c + base[HD + d - 16] * s;
        }
    }

    size_t off = ((size_t)h * S_LEN + t) * HD + d;
    bf16 qhi = __float2bfloat16(q);
    bf16 khi = __float2bfloat16(k);
    bf16 vhi = __float2bfloat16(v);
    Qh[off] = qhi;  Ql[off] = __float2bfloat16(q - __bfloat162float(qhi));
    Kh[off] = khi;  Kl[off] = __float2bfloat16(k - __bfloat162float(khi));
    Vh[off] = vhi;  Vl[off] = __float2bfloat16(v - __bfloat162float(vhi));
}

// ---------------- tensor-core flash attention (bf16x3, causal) ----------------
#define FBM 128
#define FBN 64
#define FSTR 136

#define FQH 0
#define FQL (128 * FSTR)
#define FKH (2 * 128 * FSTR)
#define FKL (FKH + 64 * FSTR)
#define FVH (FKL + 64 * FSTR)
#define FVL (FVH + 64 * FSTR)
#define FLASH_SMEM ((FVL + 64 * FSTR) * 2)

__global__ __launch_bounds__(256, 1) void flash_mma_kernel(
    const bf16* __restrict__ Qh, const bf16* __restrict__ Ql,
    const bf16* __restrict__ Kh, const bf16* __restrict__ Kl,
    const bf16* __restrict__ Vh, const bf16* __restrict__ Vl,
    bf16* __restrict__ Ch, bf16* __restrict__ Cl)
{
    extern __shared__ __align__(16) unsigned char fsraw[];
    bf16* fs = reinterpret_cast<bf16*>(fsraw);

    const int h = blockIdx.y;
    const int m_tile = gridDim.x - 1 - blockIdx.x;
    const int m0 = m_tile * FBM;
    const int tid = threadIdx.x;
    const int warp = tid >> 5;
    const int lane = tid & 31;
    const int g  = lane >> 2;
    const int tg = lane & 3;

    const bf16* qhp = Qh + ((size_t)h * S_LEN + m0) * HD;
    const bf16* qlp = Ql + ((size_t)h * S_LEN + m0) * HD;
    const bf16* khp = Kh + (size_t)h * S_LEN * HD;
    const bf16* klp = Kl + (size_t)h * S_LEN * HD;
    const bf16* vhp = Vh + (size_t)h * S_LEN * HD;
    const bf16* vlp = Vl + (size_t)h * S_LEN * HD;

    for (int idx = tid; idx < 2048; idx += 256) {
        int r = idx >> 4, c = (idx & 15) << 3;
        *reinterpret_cast<float4*>(fs + FQH + r * FSTR + c) =
            *reinterpret_cast<const float4*>(qhp + (size_t)r * HD + c);
        *reinterpret_cast<float4*>(fs + FQL + r * FSTR + c) =
            *reinterpret_cast<const float4*>(qlp + (size_t)r * HD + c);
    }

    float o[16][4];
    #pragma unroll
    for (int j = 0; j < 16; j++)
        #pragma unroll
        for (int x = 0; x < 4; x++) o[j][x] = 0.0f;
    float mrow0 = -1e30f, mrow1 = -1e30f, lrow0 = 0.0f, lrow1 = 0.0f;

    const float scale = 0.08838834764831845f;
    const int row0 = m0 + warp * 16 + g;
    const int row1 = row0 + 8;
    const int wrow_max = m0 + warp * 16 + 15;

    const int a_row = lane & 15;
    const int half8 = (lane >> 4) << 3;
    const int bk_colh = ((lane >> 3) & 1) << 3;

    const int ntiles = m0 / FBN + 2;
    for (int nt = 0; nt < ntiles; nt++) {
        const int n0 = nt * FBN;
        __syncthreads();
        for (int idx = tid; idx < 1024; idx += 256) {
            int r = idx >> 4, c = (idx & 15) << 3;
            size_t go = (size_t)(n0 + r) * HD + c;
            int so = r * FSTR + c;
            *reinterpret_cast<float4*>(fs + FKH + so) = *reinterpret_cast<const float4*>(khp + go);
            *reinterpret_cast<float4*>(fs + FKL + so) = *reinterpret_cast<const float4*>(klp + go);
            *reinterpret_cast<float4*>(fs + FVH + so) = *reinterpret_cast<const float4*>(vhp + go);
            *reinterpret_cast<float4*>(fs + FVL + so) = *reinterpret_cast<const float4*>(vlp + go);
        }
        __syncthreads();

        if (n0 > wrow_max) continue;

        float sacc[8][4];
        #pragma unroll
        for (int j = 0; j < 8; j++)
            #pragma unroll
            for (int x = 0; x < 4; x++) sacc[j][x] = 0.0f;

        #pragma unroll
        for (int ks = 0; ks < 8; ks++) {
            const int k = ks * 16;
            uint32_t aH[4], aL[4];
            {
                int ra = (warp * 16 + a_row) * FSTR + k + half8;
                ldmx4(aH, fs + FQH + ra);
                ldmx4(aL, fs + FQL + ra);
            }
            #pragma unroll
            for (int jp = 0; jp < 4; jp++) {
                int rb = (jp * 16 + half8 + (lane & 7)) * FSTR + k + bk_colh;
                uint32_t bH[4], bL[4];
                ldmx4(bH, fs + FKH + rb);
                ldmx4(bL, fs + FKL + rb);
                uint32_t b0h[2] = {bH[0], bH[1]}, b1h[2] = {bH[2], bH[3]};
                uint32_t b0l[2] = {bL[0], bL[1]}, b1l[2] = {bL[2], bL[3]};
                mma16816(sacc[2 * jp],     aH, b0h);
                mma16816(sacc[2 * jp],     aH, b0l);
                mma16816(sacc[2 * jp],     aL, b0h);
                mma16816(sacc[2 * jp + 1], aH, b1h);
                mma16816(sacc[2 * jp + 1], aH, b1l);
                mma16816(sacc[2 * jp + 1], aL, b1h);
            }
        }

        const bool boundary = (n0 + FBN - 1 > m0);
        #pragma unroll
        for (int j = 0; j < 8; j++) {
            int c0 = n0 + j * 8 + 2 * tg;
            if (boundary) {
                sacc[j][0] = (c0     > row0) ? -1e30f : sacc[j][0] * scale;
                sacc[j][1] = (c0 + 1 > row0) ? -1e30f : sacc[j][1] * scale;
                sacc[j][2] = (c0     > row1) ? -1e30f : sacc[j][2] * scale;
                sacc[j][3] = (c0 + 1 > row1) ? -1e30f : sacc[j][3] * scale;
            } else {
                sacc[j][0] *= scale; sacc[j][1] *= scale;
                sacc[j][2] *= scale; sacc[j][3] *= scale;
            }
        }

        float mx0 = -1e30f, mx1 = -1e30f;
        #pragma unroll
        for (int j = 0; j < 8; j++) {
            mx0 = fmaxf(mx0, fmaxf(sacc[j][0], sacc[j][1]));
            mx1 = fmaxf(mx1, fmaxf(sacc[j][2], sacc[j][3]));
        }
        mx0 = fmaxf(mx0, __shfl_xor_sync(0xffffffffu, mx0, 1));
        mx0 = fmaxf(mx0, __shfl_xor_sync(0xffffffffu, mx0, 2));
        mx1 = fmaxf(mx1, __shfl_xor_sync(0xffffffffu, mx1, 1));
        mx1 = fmaxf(mx1, __shfl_xor_sync(0xffffffffu, mx1, 2));

        float mn0 = fmaxf(mrow0, mx0);
        float mn1 = fmaxf(mrow1, mx1);
        float alpha0 = __expf(mrow0 - mn0);
        float alpha1 = __expf(mrow1 - mn1);
        mrow0 = mn0; mrow1 = mn1;

        float sum0 = 0.0f, sum1 = 0.0f;
        #pragma unroll
        for (int j = 0; j < 8; j++) {
            sacc[j][0] = __expf(sacc[j][0] - mn0);
            sacc[j][1] = __expf(sacc[j][1] - mn0);
            sacc[j][2] = __expf(sacc[j][2] - mn1);
            sacc[j][3] = __expf(sacc[j][3] - mn1);
            sum0 += sacc[j][0] + sacc[j][1];
            sum1 += sacc[j][2] + sacc[j][3];
        }
        sum0 += __shfl_xor_sync(0xffffffffu, sum0, 1);
        sum0 += __shfl_xor_sync(0xffffffffu, sum0, 2);
        sum1 += __shfl_xor_sync(0xffffffffu, sum1, 1);
        sum1 += __shfl_xor_sync(0xffffffffu, sum1, 2);
        lrow0 = lrow0 * alpha0 + sum0;
        lrow1 = lrow1 * alpha1 + sum1;

        #pragma unroll
        for (int j = 0; j < 16; j++) {
            o[j][0] *= alpha0; o[j][1] *= alpha0;
            o[j][2] *= alpha1; o[j][3] *= alpha1;
        }

        #pragma unroll
        for (int kk = 0; kk < 4; kk++) {
            uint32_t paH[4], paL[4];
            #pragma unroll
            for (int half = 0; half < 2; half++) {
                const float* sv = sacc[2 * kk + half];
                __nv_bfloat162 h0 = __floats2bfloat162_rn(sv[0], sv[1]);
                __nv_bfloat162 h1 = __floats2bfloat162_rn(sv[2], sv[3]);
                __nv_bfloat162 l0 = __floats2bfloat162_rn(
                    sv[0] - __bfloat162float(h0.x), sv[1] - __bfloat162float(h0.y));
                __nv_bfloat162 l1 = __floats2bfloat162_rn(
                    sv[2] - __bfloat162float(h1.x), sv[3] - __bfloat162float(h1.y));
                paH[2 * half]     = *reinterpret_cast<uint32_t*>(&h0);
                paH[2 * half + 1] = *reinterpret_cast<uint32_t*>(&h1);
                paL[2 * half]     = *reinterpret_cast<uint32_t*>(&l0);
                paL[2 * half + 1] = *reinterpret_cast<uint32_t*>(&l1);
            }
            #pragma unroll
            for (int jp = 0; jp < 8; jp++) {
                int rv = (kk * 16 + a_row) * FSTR + jp * 16 + half8;
                uint32_t vH[4], vL[4];
                ldmx4t(vH, fs + FVH + rv);
                ldmx4t(vL, fs + FVL + rv);
                uint32_t v0h[2] = {vH[0], vH[1]}, v1h[2] = {vH[2], vH[3]};
                uint32_t v0l[2] = {vL[0], vL[1]}, v1l[2] = {vL[2], vL[3]};
                mma16816(o[2 * jp],     paH, v0h);
                mma16816(o[2 * jp],     paH, v0l);
                mma16816(o[2 * jp],     paL, v0h);
                mma16816(o[2 * jp + 1], paH, v1h);
                mma16816(o[2 * jp + 1], paH, v1l);
                mma16816(o[2 * jp + 1], paL, v1h);
            }
        }
    }

    // ---- epilogue: O /= l, write bf16 hi/lo splits of ctx directly ----
    float inv0 = 1.0f / lrow0;
    float inv1 = 1.0f / lrow1;
    #pragma unroll
    for (int jt = 0; jt < 16; jt++) {
        int col = h * HD + jt * 8 + 2 * tg;
        float v00 = o[jt][0] * inv0, v01 = o[jt][1] * inv0;
        float v10 = o[jt][2] * inv1, v11 = o[jt][3] * inv1;
        __nv_bfloat162 h0 = __floats2bfloat162_rn(v00, v01);
        __nv_bfloat162 h1 = __floats2bfloat162_rn(v10, v11);
        __nv_bfloat162 l0 = __floats2bfloat162_rn(
            v00 - __bfloat162float(h0.x), v01 - __bfloat162float(h0.y));
        __nv_bfloat162 l1 = __floats2bfloat162_rn(
            v10 - __bfloat162float(h1.x), v11 - __bfloat162float(h1.y));
        *reinterpret_cast<__nv_bfloat162*>(Ch + (size_t)row0 * HID + col) = h0;
        *reinterpret_cast<__nv_bfloat162*>(Cl + (size_t)row0 * HID + col) = l0;
        *reinterpret_cast<__nv_bfloat162*>(Ch + (size_t)row1 * HID + col) = h1;
        *reinterpret_cast<__nv_bfloat162*>(Cl + (size_t)row1 * HID + col) = l1;
    }
}

// ---------------- launch ----------------
extern "C" void kernel_launch(void* const* d_in, const int* in_sizes, int n_in,
                              void* d_out, int out_size)
{
    const float* hidden  = (const float*)d_in[0];
    const float* W_qkv   = (const float*)d_in[1];
    const float* b_qkv   = (const float*)d_in[2];
    const float* W_dense = (const float*)d_in[3];
    const float* b_dense = (const float*)d_in[4];
    float* out = (float*)d_out;

    float *mixed;
    bf16 *ah, *al, *bh, *bl, *wh, *wl, *ch, *cl;
    bf16 *qh, *ql, *kh, *kl, *vh, *vl;
    cudaGetSymbolAddress((void**)&mixed, g_mixed);
    cudaGetSymbolAddress((void**)&ah,    g_ah);
    cudaGetSymbolAddress((void**)&al,    g_al);
    cudaGetSymbolAddress((void**)&bh,    g_bh);
    cudaGetSymbolAddress((void**)&bl,    g_bl);
    cudaGetSymbolAddress((void**)&wh,    g_wh);
    cudaGetSymbolAddress((void**)&wl,    g_wl);
    cudaGetSymbolAddress((void**)&ch,    g_ch);
    cudaGetSymbolAddress((void**)&cl,    g_cl);
    cudaGetSymbolAddress((void**)&qh,    g_qh);
    cudaGetSymbolAddress((void**)&ql,    g_ql);
    cudaGetSymbolAddress((void**)&kh,    g_kh);
    cudaGetSymbolAddress((void**)&kl,    g_kl);
    cudaGetSymbolAddress((void**)&vh,    g_vh);
    cudaGetSymbolAddress((void**)&vl,    g_vl);

    cudaFuncSetAttribute(mma_gemm_bf16x3,
                         cudaFuncAttributeMaxDynamicSharedMemorySize, GEMM_SMEM);
    cudaFuncSetAttribute(flash_mma_kernel,
                         cudaFuncAttributeMaxDynamicSharedMemorySize, FLASH_SMEM);

    // 0) bf16 hi/lo splits of inputs
    {
        int n4 = S_LEN * HID / 4;
        split_bf16_kernel<<<(n4 + 255) / 256, 256>>>(hidden, ah, al, n4);
        int w4 = HID * NQKV / 4;
        split_bf16_kernel<<<(w4 + 255) / 256, 256>>>(W_qkv, bh, bl, w4);
        int d4 = HID * HID / 4;
        split_bf16_kernel<<<(d4 + 255) / 256, 256>>>(W_dense, wh, wl, d4);
    }

    // 1) QKV projection (+bias), tensor cores
    {
        dim3 grid(NQKV / 128, S_LEN / 128);
        mma_gemm_bf16x3<<<grid, 512, GEMM_SMEM>>>(ah, al, bh, bl, b_qkv, mixed,
                                                  S_LEN, NQKV, HID);
    }

    // 2) RoPE + scatter + split
    qkv_rope_split_kernel<<<dim3(S_LEN, NH), 128>>>(mixed, qh, ql, kh, kl, vh, vl);

    // 3) causal flash attention, tensor cores; writes ctx bf16 hi/lo directly
    flash_mma_kernel<<<dim3(S_LEN / FBM, NH), 256, FLASH_SMEM>>>(
        qh, ql, kh, kl, vh, vl, ch, cl);

    // 4) dense projection (+bias), tensor cores
    {
        dim3 grid(HID / 128, S_LEN / 128);
        mma_gemm_bf16x3<<<grid, 512, GEMM_SMEM>>>(ch, cl, wh, wl, b_dense, out,
                                                  S_LEN, HID, HID);
    }
}

// round 7
// speedup vs baseline: 2.7697x; 1.0989x over previous
#include <cuda_runtime.h>
#include <cuda_bf16.h>
#include <cstdint>
#include <math.h>

using std::uint32_t;

// ---------------- problem constants ----------------
#define S_LEN 2048
#define HID   2048
#define NH    16
#define HD    128
#define NQKV  6144   // 3 * HID
#define ROT   32

typedef __nv_bfloat16 bf16;

// ---------------- scratch (device globals; no runtime alloc) ----------------
__device__ float g_mixed[(size_t)S_LEN * NQKV];

__device__ bf16 g_ah[(size_t)S_LEN * HID];
__device__ bf16 g_al[(size_t)S_LEN * HID];
__device__ bf16 g_bh[(size_t)HID * NQKV];
__device__ bf16 g_bl[(size_t)HID * NQKV];
__device__ bf16 g_wh[(size_t)HID * HID];
__device__ bf16 g_wl[(size_t)HID * HID];
__device__ bf16 g_ch[(size_t)S_LEN * HID];
__device__ bf16 g_cl[(size_t)S_LEN * HID];

__device__ bf16 g_qh[(size_t)NH * S_LEN * HD];
__device__ bf16 g_ql[(size_t)NH * S_LEN * HD];
__device__ bf16 g_kh[(size_t)NH * S_LEN * HD];
__device__ bf16 g_kl[(size_t)NH * S_LEN * HD];
__device__ bf16 g_vh[(size_t)NH * S_LEN * HD];
__device__ bf16 g_vl[(size_t)NH * S_LEN * HD];

// ---------------- common PTX helpers ----------------
__device__ __forceinline__ void cp_async16(void* smem_dst, const void* gmem_src) {
    uint32_t s = (uint32_t)__cvta_generic_to_shared(smem_dst);
    asm volatile("cp.async.cg.shared.global [%0], [%1], 16;\n" :: "r"(s), "l"(gmem_src));
}
__device__ __forceinline__ void cp_commit() {
    asm volatile("cp.async.commit_group;\n");
}
template <int N>
__device__ __forceinline__ void cp_wait() {
    asm volatile("cp.async.wait_group %0;\n" :: "n"(N));
}

__device__ __forceinline__ void mma16816(float* c, const uint32_t* a, const uint32_t* b) {
    asm volatile(
        "mma.sync.aligned.m16n8k16.row.col.f32.bf16.bf16.f32 "
        "{%0,%1,%2,%3}, {%4,%5,%6,%7}, {%8,%9}, {%0,%1,%2,%3};\n"
        : "+f"(c[0]), "+f"(c[1]), "+f"(c[2]), "+f"(c[3])
        : "r"(a[0]), "r"(a[1]), "r"(a[2]), "r"(a[3]), "r"(b[0]), "r"(b[1]));
}

__device__ __forceinline__ void ldmx4(uint32_t* r, const void* p) {
    uint32_t a = (uint32_t)__cvta_generic_to_shared(p);
    asm volatile("ldmatrix.sync.aligned.m8n8.x4.shared.b16 {%0,%1,%2,%3}, [%4];"
                 : "=r"(r[0]), "=r"(r[1]), "=r"(r[2]), "=r"(r[3]) : "r"(a));
}
__device__ __forceinline__ void ldmx4t(uint32_t* r, const void* p) {
    uint32_t a = (uint32_t)__cvta_generic_to_shared(p);
    asm volatile("ldmatrix.sync.aligned.m8n8.x4.trans.shared.b16 {%0,%1,%2,%3}, [%4];"
                 : "=r"(r[0]), "=r"(r[1]), "=r"(r[2]), "=r"(r[3]) : "r"(a));
}

// ---------------- fp32 -> bf16 hi/lo split ----------------
__global__ __launch_bounds__(256) void split_bf16_kernel(
    const float* __restrict__ x, bf16* __restrict__ hi, bf16* __restrict__ lo, int n4)
{
    int i = blockIdx.x * blockDim.x + threadIdx.x;
    if (i >= n4) return;
    float4 v = reinterpret_cast<const float4*>(x)[i];
    bf16 h0 = __float2bfloat16(v.x);
    bf16 h1 = __float2bfloat16(v.y);
    bf16 h2 = __float2bfloat16(v.z);
    bf16 h3 = __float2bfloat16(v.w);
    bf16 l0 = __float2bfloat16(v.x - __bfloat162float(h0));
    bf16 l1 = __float2bfloat16(v.y - __bfloat162float(h1));
    bf16 l2 = __float2bfloat16(v.z - __bfloat162float(h2));
    bf16 l3 = __float2bfloat16(v.w - __bfloat162float(h3));
    __nv_bfloat162* hp = reinterpret_cast<__nv_bfloat162*>(hi);
    __nv_bfloat162* lp = reinterpret_cast<__nv_bfloat162*>(lo);
    hp[2 * i]     = __nv_bfloat162(h0, h1);
    hp[2 * i + 1] = __nv_bfloat162(h2, h3);
    lp[2 * i]     = __nv_bfloat162(l0, l1);
    lp[2 * i + 1] = __nv_bfloat162(l2, l3);
}

// ---------------- HMMA GEMM (bf16x3, fp32 accum) ----------------
// 128x128 block tile, BK=64, 512 threads (16 warps, 4x4), warp tile 32x32.
// 3-stage cp.async ring, one __syncthreads per stage.
#define GBK 64
#define SA     72                    // 64 + 8 pad
#define SB     136                   // 128 + 8 pad
#define OAH    0
#define OAL    (128 * SA)            // 9216
#define OBH    (2 * 128 * SA)        // 18432
#define OBL    (OBH + GBK * SB)      // 27136
#define BUFSZ  (OBL + GBK * SB)      // 35840 bf16 = 71680 B
#define GEMM_SMEM (3 * BUFSZ * 2)    // 215040 B

__global__ __launch_bounds__(512, 1) void mma_gemm_bf16x3(
    const bf16* __restrict__ Ah, const bf16* __restrict__ Al,
    const bf16* __restrict__ Bh, const bf16* __restrict__ Bl,
    const float* __restrict__ bias, float* __restrict__ C,
    int M, int N, int K)
{
    extern __shared__ __align__(16) unsigned char smraw[];
    bf16* sm = reinterpret_cast<bf16*>(smraw);

    const int bx = blockIdx.x;
    const int by = blockIdx.y;
    const int tid = threadIdx.x;
    const int warp = tid >> 5;
    const int lane = tid & 31;
    const int warp_m = warp >> 2;      // 0..3
    const int warp_n = warp & 3;       // 0..3
    const int g  = lane >> 2;
    const int tg = lane & 3;

    const int nst = K / GBK;           // 32

    float acc[2][4][4];
    #pragma unroll
    for (int i = 0; i < 2; i++)
        #pragma unroll
        for (int j = 0; j < 4; j++)
            #pragma unroll
            for (int x = 0; x < 4; x++) acc[i][j][x] = 0.0f;

    auto issue = [&](int s) {
        const int k0 = s * GBK;
        bf16* buf = sm + (s % 3) * BUFSZ;
        // A: 128 rows x 8 chunks (16B) per matrix; 1024 chunks, 2/thread
        #pragma unroll
        for (int q = tid; q < 1024; q += 512) {
            int r = q >> 3, c = q & 7;
            size_t ga = (size_t)(by * 128 + r) * K + k0 + c * 8;
            int sa = r * SA + c * 8;
            cp_async16(buf + OAH + sa, Ah + ga);
            cp_async16(buf + OAL + sa, Al + ga);
        }
        // B: 64 rows x 16 chunks per matrix; 1024 chunks, 2/thread
        #pragma unroll
        for (int q = tid; q < 1024; q += 512) {
            int r = q >> 4, c = q & 15;
            size_t gb = (size_t)(k0 + r) * N + bx * 128 + c * 8;
            int sb = r * SB + c * 8;
            cp_async16(buf + OBH + sb, Bh + gb);
            cp_async16(buf + OBL + sb, Bl + gb);
        }
    };

    issue(0); cp_commit();
    issue(1); cp_commit();

    const int a_row = lane & 15;
    const int a_colh = (lane >> 4) << 3;
    const int b_row = lane & 15;
    const int b_colh = (lane >> 4) << 3;

    for (int s = 0; s < nst; s++) {
        cp_wait<1>();
        __syncthreads();
        if (s + 2 < nst) { issue(s + 2); cp_commit(); }

        const bf16* buf = sm + (s % 3) * BUFSZ;

        #pragma unroll
        for (int ks = 0; ks < GBK; ks += 16) {
            uint32_t ah[2][4], al[2][4], bh[4][2], bl[4][2];
            #pragma unroll
            for (int i = 0; i < 2; i++) {
                int ra = (warp_m * 32 + i * 16 + a_row) * SA + ks + a_colh;
                ldmx4(ah[i], buf + OAH + ra);
                ldmx4(al[i], buf + OAL + ra);
            }
            #pragma unroll
            for (int jp = 0; jp < 2; jp++) {
                int rb = (ks + b_row) * SB + warp_n * 32 + jp * 16 + b_colh;
                uint32_t th[4], tl[4];
                ldmx4t(th, buf + OBH + rb);
                ldmx4t(tl, buf + OBL + rb);
                bh[2 * jp][0] = th[0]; bh[2 * jp][1] = th[1];
                bh[2 * jp + 1][0] = th[2]; bh[2 * jp + 1][1] = th[3];
                bl[2 * jp][0] = tl[0]; bl[2 * jp][1] = tl[1];
                bl[2 * jp + 1][0] = tl[2]; bl[2 * jp + 1][1] = tl[3];
            }
            #pragma unroll
            for (int i = 0; i < 2; i++)
                #pragma unroll
                for (int j = 0; j < 4; j++) {
                    mma16816(acc[i][j], ah[i], bh[j]);
                    mma16816(acc[i][j], ah[i], bl[j]);
                    mma16816(acc[i][j], al[i], bh[j]);
                }
        }
    }

    #pragma unroll
    for (int i = 0; i < 2; i++) {
        #pragma unroll
        for (int j = 0; j < 4; j++) {
            int row0 = by * 128 + warp_m * 32 + i * 16 + g;
            int col  = bx * 128 + warp_n * 32 + j * 8 + tg * 2;
            float b0 = bias[col], b1 = bias[col + 1];
            float2 v0 = make_float2(acc[i][j][0] + b0, acc[i][j][1] + b1);
            float2 v1 = make_float2(acc[i][j][2] + b0, acc[i][j][3] + b1);
            *reinterpret_cast<float2*>(C + (size_t)row0 * N + col) = v0;
            *reinterpret_cast<float2*>(C + (size_t)(row0 + 8) * N + col) = v1;
        }
    }
}

// ---------------- RoPE + scatter + bf16 hi/lo split ----------------
__global__ __launch_bounds__(128) void qkv_rope_split_kernel(
    const float* __restrict__ mixed,
    bf16* __restrict__ Qh, bf16* __restrict__ Ql,
    bf16* __restrict__ Kh, bf16* __restrict__ Kl,
    bf16* __restrict__ Vh, bf16* __restrict__ Vl)
{
    const int t = blockIdx.x;
    const int h = blockIdx.y;
    const int d = threadIdx.x;

    const float* base = mixed + (size_t)t * NQKV + h * (3 * HD);
    float q = base[d];
    float k = base[HD + d];
    float v = base[2 * HD + d];

    if (d < ROT) {
        const int i = d & 15;
        float inv_freq = 1.0f / powf(10000.0f, (float)(2 * i) * (1.0f / (float)ROT));
        float ang = (float)t * inv_freq;
        float s, c;
        sincosf(ang, &s, &c);
        if (d < 16) {
            q = q * c - base[d + 16] * s;
            k = k * c - base[HD + d + 16] * s;
        } else {
            q = q * c + base[d - 16] * s;
            k = k * c + base[HD + d - 16] * s;
        }
    }

    size_t off = ((size_t)h * S_LEN + t) * HD + d;
    bf16 qhi = __float2bfloat16(q);
    bf16 khi = __float2bfloat16(k);
    bf16 vhi = __float2bfloat16(v);
    Qh[off] = qhi;  Ql[off] = __float2bfloat16(q - __bfloat162float(qhi));
    Kh[off] = khi;  Kl[off] = __float2bfloat16(k - __bfloat162float(khi));
    Vh[off] = vhi;  Vl[off] = __float2bfloat16(v - __bfloat162float(vhi));
}

// ---------------- HMMA flash attention (bf16x3, causal) ----------------
// BM=128, BN=64, 256 threads (8 warps). K/V double-buffered via cp.async.
#define FBM 128
#define FBN 64
#define FSTR 136

#define FQH 0
#define FQL (128 * FSTR)
#define FKV0 (2 * 128 * FSTR)        // 34816 elems
#define KVARR (64 * FSTR)            // 8704 elems per array
#define KVSTG (4 * KVARR)            // one stage: KH,KL,VH,VL
#define FLASH_SMEM ((FKV0 + 2 * KVSTG) * 2)   // 208896 B

__global__ __launch_bounds__(256, 1) void flash_mma_kernel(
    const bf16* __restrict__ Qh, const bf16* __restrict__ Ql,
    const bf16* __restrict__ Kh, const bf16* __restrict__ Kl,
    const bf16* __restrict__ Vh, const bf16* __restrict__ Vl,
    bf16* __restrict__ Ch, bf16* __restrict__ Cl)
{
    extern __shared__ __align__(16) unsigned char fsraw[];
    bf16* fs = reinterpret_cast<bf16*>(fsraw);

    const int h = blockIdx.y;
    const int m_tile = gridDim.x - 1 - blockIdx.x;
    const int m0 = m_tile * FBM;
    const int tid = threadIdx.x;
    const int warp = tid >> 5;
    const int lane = tid & 31;
    const int g  = lane >> 2;
    const int tg = lane & 3;

    const bf16* qhp = Qh + ((size_t)h * S_LEN + m0) * HD;
    const bf16* qlp = Ql + ((size_t)h * S_LEN + m0) * HD;
    const bf16* khp = Kh + (size_t)h * S_LEN * HD;
    const bf16* klp = Kl + (size_t)h * S_LEN * HD;
    const bf16* vhp = Vh + (size_t)h * S_LEN * HD;
    const bf16* vlp = Vl + (size_t)h * S_LEN * HD;

    // load Q tile (sync)
    for (int idx = tid; idx < 2048; idx += 256) {
        int r = idx >> 4, c = (idx & 15) << 3;
        *reinterpret_cast<float4*>(fs + FQH + r * FSTR + c) =
            *reinterpret_cast<const float4*>(qhp + (size_t)r * HD + c);
        *reinterpret_cast<float4*>(fs + FQL + r * FSTR + c) =
            *reinterpret_cast<const float4*>(qlp + (size_t)r * HD + c);
    }

    // K/V tile async loader: 4 arrays x 1024 chunks -> 16 chunks/thread
    auto issue_kv = [&](int nt) {
        const int n0 = nt * FBN;
        bf16* buf = fs + FKV0 + (nt & 1) * KVSTG;
        #pragma unroll
        for (int q = tid; q < 1024; q += 256) {
            int r = q >> 4, c = (q & 15) << 3;
            size_t go = (size_t)(n0 + r) * HD + c;
            int so = r * FSTR + c;
            cp_async16(buf + 0 * KVARR + so, khp + go);
            cp_async16(buf + 1 * KVARR + so, klp + go);
            cp_async16(buf + 2 * KVARR + so, vhp + go);
            cp_async16(buf + 3 * KVARR + so, vlp + go);
        }
    };

    float o[16][4];
    #pragma unroll
    for (int j = 0; j < 16; j++)
        #pragma unroll
        for (int x = 0; x < 4; x++) o[j][x] = 0.0f;
    float mrow0 = -1e30f, mrow1 = -1e30f, lrow0 = 0.0f, lrow1 = 0.0f;

    const float scale = 0.08838834764831845f;
    const int row0 = m0 + warp * 16 + g;
    const int row1 = row0 + 8;
    const int wrow_max = m0 + warp * 16 + 15;

    const int a_row = lane & 15;
    const int half8 = (lane >> 4) << 3;
    const int bk_colh = ((lane >> 3) & 1) << 3;

    const int ntiles = m0 / FBN + 2;
    issue_kv(0); cp_commit();

    for (int nt = 0; nt < ntiles; nt++) {
        const int n0 = nt * FBN;
        if (nt + 1 < ntiles) { issue_kv(nt + 1); cp_commit(); cp_wait<1>(); }
        else                 { cp_wait<0>(); }
        __syncthreads();

        if (n0 <= wrow_max) {
            const bf16* kvb = fs + FKV0 + (nt & 1) * KVSTG;
            const bf16* kh_s = kvb;
            const bf16* kl_s = kvb + KVARR;
            const bf16* vh_s = kvb + 2 * KVARR;
            const bf16* vl_s = kvb + 3 * KVARR;

            float sacc[8][4];
            #pragma unroll
            for (int j = 0; j < 8; j++)
                #pragma unroll
                for (int x = 0; x < 4; x++) sacc[j][x] = 0.0f;

            #pragma unroll
            for (int ks = 0; ks < 8; ks++) {
                const int k = ks * 16;
                uint32_t aH[4], aL[4];
                {
                    int ra = (warp * 16 + a_row) * FSTR + k + half8;
                    ldmx4(aH, fs + FQH + ra);
                    ldmx4(aL, fs + FQL + ra);
                }
                #pragma unroll
                for (int jp = 0; jp < 4; jp++) {
                    int rb = (jp * 16 + half8 + (lane & 7)) * FSTR + k + bk_colh;
                    uint32_t bH[4], bL[4];
                    ldmx4(bH, kh_s + rb);
                    ldmx4(bL, kl_s + rb);
                    uint32_t b0h[2] = {bH[0], bH[1]}, b1h[2] = {bH[2], bH[3]};
                    uint32_t b0l[2] = {bL[0], bL[1]}, b1l[2] = {bL[2], bL[3]};
                    mma16816(sacc[2 * jp],     aH, b0h);
                    mma16816(sacc[2 * jp],     aH, b0l);
                    mma16816(sacc[2 * jp],     aL, b0h);
                    mma16816(sacc[2 * jp + 1], aH, b1h);
                    mma16816(sacc[2 * jp + 1], aH, b1l);
                    mma16816(sacc[2 * jp + 1], aL, b1h);
                }
            }

            const bool boundary = (n0 + FBN - 1 > m0);
            #pragma unroll
            for (int j = 0; j < 8; j++) {
                int c0 = n0 + j * 8 + 2 * tg;
                if (boundary) {
                    sacc[j][0] = (c0     > row0) ? -1e30f : sacc[j][0] * scale;
                    sacc[j][1] = (c0 + 1 > row0) ? -1e30f : sacc[j][1] * scale;
                    sacc[j][2] = (c0     > row1) ? -1e30f : sacc[j][2] * scale;
                    sacc[j][3] = (c0 + 1 > row1) ? -1e30f : sacc[j][3] * scale;
                } else {
                    sacc[j][0] *= scale; sacc[j][1] *= scale;
                    sacc[j][2] *= scale; sacc[j][3] *= scale;
                }
            }

            float mx0 = -1e30f, mx1 = -1e30f;
            #pragma unroll
            for (int j = 0; j < 8; j++) {
                mx0 = fmaxf(mx0, fmaxf(sacc[j][0], sacc[j][1]));
                mx1 = fmaxf(mx1, fmaxf(sacc[j][2], sacc[j][3]));
            }
            mx0 = fmaxf(mx0, __shfl_xor_sync(0xffffffffu, mx0, 1));
            mx0 = fmaxf(mx0, __shfl_xor_sync(0xffffffffu, mx0, 2));
            mx1 = fmaxf(mx1, __shfl_xor_sync(0xffffffffu, mx1, 1));
            mx1 = fmaxf(mx1, __shfl_xor_sync(0xffffffffu, mx1, 2));

            float mn0 = fmaxf(mrow0, mx0);
            float mn1 = fmaxf(mrow1, mx1);
            float alpha0 = __expf(mrow0 - mn0);
            float alpha1 = __expf(mrow1 - mn1);
            mrow0 = mn0; mrow1 = mn1;

            float sum0 = 0.0f, sum1 = 0.0f;
            #pragma unroll
            for (int j = 0; j < 8; j++) {
                sacc[j][0] = __expf(sacc[j][0] - mn0);
                sacc[j][1] = __expf(sacc[j][1] - mn0);
                sacc[j][2] = __expf(sacc[j][2] - mn1);
                sacc[j][3] = __expf(sacc[j][3] - mn1);
                sum0 += sacc[j][0] + sacc[j][1];
                sum1 += sacc[j][2] + sacc[j][3];
            }
            sum0 += __shfl_xor_sync(0xffffffffu, sum0, 1);
            sum0 += __shfl_xor_sync(0xffffffffu, sum0, 2);
            sum1 += __shfl_xor_sync(0xffffffffu, sum1, 1);
            sum1 += __shfl_xor_sync(0xffffffffu, sum1, 2);
            lrow0 = lrow0 * alpha0 + sum0;
            lrow1 = lrow1 * alpha1 + sum1;

            #pragma unroll
            for (int j = 0; j < 16; j++) {
                o[j][0] *= alpha0; o[j][1] *= alpha0;
                o[j][2] *= alpha1; o[j][3] *= alpha1;
            }

            #pragma unroll
            for (int kk = 0; kk < 4; kk++) {
                uint32_t paH[4], paL[4];
                #pragma unroll
                for (int half = 0; half < 2; half++) {
                    const float* sv = sacc[2 * kk + half];
                    __nv_bfloat162 h0 = __floats2bfloat162_rn(sv[0], sv[1]);
                    __nv_bfloat162 h1 = __floats2bfloat162_rn(sv[2], sv[3]);
                    __nv_bfloat162 l0 = __floats2bfloat162_rn(
                        sv[0] - __bfloat162float(h0.x), sv[1] - __bfloat162float(h0.y));
                    __nv_bfloat162 l1 = __floats2bfloat162_rn(
                        sv[2] - __bfloat162float(h1.x), sv[3] - __bfloat162float(h1.y));
                    paH[2 * half]     = *reinterpret_cast<uint32_t*>(&h0);
                    paH[2 * half + 1] = *reinterpret_cast<uint32_t*>(&h1);
                    paL[2 * half]     = *reinterpret_cast<uint32_t*>(&l0);
                    paL[2 * half + 1] = *reinterpret_cast<uint32_t*>(&l1);
                }
                #pragma unroll
                for (int jp = 0; jp < 8; jp++) {
                    int rv = (kk * 16 + a_row) * FSTR + jp * 16 + half8;
                    uint32_t vH[4], vL[4];
                    ldmx4t(vH, vh_s + rv);
                    ldmx4t(vL, vl_s + rv);
                    uint32_t v0h[2] = {vH[0], vH[1]}, v1h[2] = {vH[2], vH[3]};
                    uint32_t v0l[2] = {vL[0], vL[1]}, v1l[2] = {vL[2], vL[3]};
                    mma16816(o[2 * jp],     paH, v0h);
                    mma16816(o[2 * jp],     paH, v0l);
                    mma16816(o[2 * jp],     paL, v0h);
                    mma16816(o[2 * jp + 1], paH, v1h);
                    mma16816(o[2 * jp + 1], paH, v1l);
                    mma16816(o[2 * jp + 1], paL, v1h);
                }
            }
        }
        __syncthreads();   // all warps done reading stage (nt&1) before it is refilled
    }

    float inv0 = 1.0f / lrow0;
    float inv1 = 1.0f / lrow1;
    #pragma unroll
    for (int jt = 0; jt < 16; jt++) {
        int col = h * HD + jt * 8 + 2 * tg;
        float v00 = o[jt][0] * inv0, v01 = o[jt][1] * inv0;
        float v10 = o[jt][2] * inv1, v11 = o[jt][3] * inv1;
        __nv_bfloat162 h0 = __floats2bfloat162_rn(v00, v01);
        __nv_bfloat162 h1 = __floats2bfloat162_rn(v10, v11);
        __nv_bfloat162 l0 = __floats2bfloat162_rn(
            v00 - __bfloat162float(h0.x), v01 - __bfloat162float(h0.y));
        __nv_bfloat162 l1 = __floats2bfloat162_rn(
            v10 - __bfloat162float(h1.x), v11 - __bfloat162float(h1.y));
        *reinterpret_cast<__nv_bfloat162*>(Ch + (size_t)row0 * HID + col) = h0;
        *reinterpret_cast<__nv_bfloat162*>(Cl + (size_t)row0 * HID + col) = l0;
        *reinterpret_cast<__nv_bfloat162*>(Ch + (size_t)row1 * HID + col) = h1;
        *reinterpret_cast<__nv_bfloat162*>(Cl + (size_t)row1 * HID + col) = l1;
    }
}

// ---------------- launch ----------------
extern "C" void kernel_launch(void* const* d_in, const int* in_sizes, int n_in,
                              void* d_out, int out_size)
{
    const float* hidden  = (const float*)d_in[0];
    const float* W_qkv   = (const float*)d_in[1];
    const float* b_qkv   = (const float*)d_in[2];
    const float* W_dense = (const float*)d_in[3];
    const float* b_dense = (const float*)d_in[4];
    float* out = (float*)d_out;

    float *mixed;
    bf16 *ah, *al, *bh, *bl, *wh, *wl, *ch, *cl;
    bf16 *qh, *ql, *kh, *kl, *vh, *vl;
    cudaGetSymbolAddress((void**)&mixed, g_mixed);
    cudaGetSymbolAddress((void**)&ah,    g_ah);
    cudaGetSymbolAddress((void**)&al,    g_al);
    cudaGetSymbolAddress((void**)&bh,    g_bh);
    cudaGetSymbolAddress((void**)&bl,    g_bl);
    cudaGetSymbolAddress((void**)&wh,    g_wh);
    cudaGetSymbolAddress((void**)&wl,    g_wl);
    cudaGetSymbolAddress((void**)&ch,    g_ch);
    cudaGetSymbolAddress((void**)&cl,    g_cl);
    cudaGetSymbolAddress((void**)&qh,    g_qh);
    cudaGetSymbolAddress((void**)&ql,    g_ql);
    cudaGetSymbolAddress((void**)&kh,    g_kh);
    cudaGetSymbolAddress((void**)&kl,    g_kl);
    cudaGetSymbolAddress((void**)&vh,    g_vh);
    cudaGetSymbolAddress((void**)&vl,    g_vl);

    cudaFuncSetAttribute(mma_gemm_bf16x3,
                         cudaFuncAttributeMaxDynamicSharedMemorySize, GEMM_SMEM);
    cudaFuncSetAttribute(flash_mma_kernel,
                         cudaFuncAttributeMaxDynamicSharedMemorySize, FLASH_SMEM);

    // 0) bf16 hi/lo splits
    {
        int n4 = S_LEN * HID / 4;
        split_bf16_kernel<<<(n4 + 255) / 256, 256>>>(hidden, ah, al, n4);
        int w4 = HID * NQKV / 4;
        split_bf16_kernel<<<(w4 + 255) / 256, 256>>>(W_qkv, bh, bl, w4);
        int d4 = HID * HID / 4;
        split_bf16_kernel<<<(d4 + 255) / 256, 256>>>(W_dense, wh, wl, d4);
    }

    // 1) QKV projection (+bias)
    {
        dim3 grid(NQKV / 128, S_LEN / 128);
        mma_gemm_bf16x3<<<grid, 512, GEMM_SMEM>>>(ah, al, bh, bl, b_qkv, mixed,
                                                  S_LEN, NQKV, HID);
    }

    // 2) RoPE + scatter + split
    qkv_rope_split_kernel<<<dim3(S_LEN, NH), 128>>>(mixed, qh, ql, kh, kl, vh, vl);

    // 3) causal flash attention; writes ctx bf16 hi/lo
    flash_mma_kernel<<<dim3(S_LEN / FBM, NH), 256, FLASH_SMEM>>>(
        qh, ql, kh, kl, vh, vl, ch, cl);

    // 4) dense projection (+bias)
    {
        dim3 grid(HID / 128, S_LEN / 128);
        mma_gemm_bf16x3<<<grid, 512, GEMM_SMEM>>>(ch, cl, wh, wl, b_dense, out,
                                                  S_LEN, HID, HID);
    }
}

// round 9
// speedup vs baseline: 2.9921x; 1.0803x over previous
#include <cuda_runtime.h>
#include <cuda_bf16.h>
#include <cstdint>
#include <math.h>

using std::uint32_t;

// ---------------- problem constants ----------------
#define S_LEN 2048
#define HID   2048
#define NH    16
#define HD    128
#define NQKV  6144   // 3 * HID
#define ROT   32

typedef __nv_bfloat16 bf16;

// ---------------- scratch (device globals; no runtime alloc) ----------------
__device__ float g_mixed[(size_t)S_LEN * NQKV];

__device__ bf16 g_ah[(size_t)S_LEN * HID];
__device__ bf16 g_al[(size_t)S_LEN * HID];
__device__ bf16 g_bh[(size_t)HID * NQKV];
__device__ bf16 g_bl[(size_t)HID * NQKV];
__device__ bf16 g_wh[(size_t)HID * HID];
__device__ bf16 g_wl[(size_t)HID * HID];
__device__ bf16 g_ch[(size_t)S_LEN * HID];
__device__ bf16 g_cl[(size_t)S_LEN * HID];

__device__ bf16 g_qh[(size_t)NH * S_LEN * HD];
__device__ bf16 g_ql[(size_t)NH * S_LEN * HD];
__device__ bf16 g_kh[(size_t)NH * S_LEN * HD];
__device__ bf16 g_kl[(size_t)NH * S_LEN * HD];
__device__ bf16 g_vh[(size_t)NH * S_LEN * HD];
__device__ bf16 g_vl[(size_t)NH * S_LEN * HD];

// ---------------- common PTX helpers ----------------
__device__ __forceinline__ void cp_async16(void* smem_dst, const void* gmem_src) {
    uint32_t s = (uint32_t)__cvta_generic_to_shared(smem_dst);
    asm volatile("cp.async.cg.shared.global [%0], [%1], 16;\n" :: "r"(s), "l"(gmem_src));
}
__device__ __forceinline__ void cp_commit() {
    asm volatile("cp.async.commit_group;\n");
}
template <int N>
__device__ __forceinline__ void cp_wait() {
    asm volatile("cp.async.wait_group %0;\n" :: "n"(N));
}

__device__ __forceinline__ void mma16816(float* c, const uint32_t* a, const uint32_t* b) {
    asm volatile(
        "mma.sync.aligned.m16n8k16.row.col.f32.bf16.bf16.f32 "
        "{%0,%1,%2,%3}, {%4,%5,%6,%7}, {%8,%9}, {%0,%1,%2,%3};\n"
        : "+f"(c[0]), "+f"(c[1]), "+f"(c[2]), "+f"(c[3])
        : "r"(a[0]), "r"(a[1]), "r"(a[2]), "r"(a[3]), "r"(b[0]), "r"(b[1]));
}

__device__ __forceinline__ void ldmx4(uint32_t* r, const void* p) {
    uint32_t a = (uint32_t)__cvta_generic_to_shared(p);
    asm volatile("ldmatrix.sync.aligned.m8n8.x4.shared.b16 {%0,%1,%2,%3}, [%4];"
                 : "=r"(r[0]), "=r"(r[1]), "=r"(r[2]), "=r"(r[3]) : "r"(a));
}
__device__ __forceinline__ void ldmx4t(uint32_t* r, const void* p) {
    uint32_t a = (uint32_t)__cvta_generic_to_shared(p);
    asm volatile("ldmatrix.sync.aligned.m8n8.x4.trans.shared.b16 {%0,%1,%2,%3}, [%4];"
                 : "=r"(r[0]), "=r"(r[1]), "=r"(r[2]), "=r"(r[3]) : "r"(a));
}

// ---------------- fp32 -> bf16 hi/lo split ----------------
__global__ __launch_bounds__(256) void split_bf16_kernel(
    const float* __restrict__ x, bf16* __restrict__ hi, bf16* __restrict__ lo, int n4)
{
    int i = blockIdx.x * blockDim.x + threadIdx.x;
    if (i >= n4) return;
    float4 v = reinterpret_cast<const float4*>(x)[i];
    bf16 h0 = __float2bfloat16(v.x);
    bf16 h1 = __float2bfloat16(v.y);
    bf16 h2 = __float2bfloat16(v.z);
    bf16 h3 = __float2bfloat16(v.w);
    bf16 l0 = __float2bfloat16(v.x - __bfloat162float(h0));
    bf16 l1 = __float2bfloat16(v.y - __bfloat162float(h1));
    bf16 l2 = __float2bfloat16(v.z - __bfloat162float(h2));
    bf16 l3 = __float2bfloat16(v.w - __bfloat162float(h3));
    __nv_bfloat162* hp = reinterpret_cast<__nv_bfloat162*>(hi);
    __nv_bfloat162* lp = reinterpret_cast<__nv_bfloat162*>(lo);
    hp[2 * i]     = __nv_bfloat162(h0, h1);
    hp[2 * i + 1] = __nv_bfloat162(h2, h3);
    lp[2 * i]     = __nv_bfloat162(l0, l1);
    lp[2 * i + 1] = __nv_bfloat162(l2, l3);
}

// ---------------- HMMA GEMM (bf16x3, fp32 accum) ----------------
// 128x256 block tile, BK=32, 512 threads (16 warps 4x4), warp tile 32x64.
// 3-stage cp.async ring, one __syncthreads per stage.
#define GBK 32
#define SA     40                    // 32 + 8 pad
#define SB     264                   // 256 + 8 pad
#define OAH    0
#define OAL    (128 * SA)            // 5120
#define OBH    (2 * 128 * SA)        // 10240
#define OBL    (OBH + GBK * SB)      // 18688
#define BUFSZ  (OBL + GBK * SB)      // 27136 bf16 = 54272 B
#define GEMM_SMEM (3 * BUFSZ * 2)    // 162816 B

__global__ __launch_bounds__(512, 1) void mma_gemm_bf16x3(
    const bf16* __restrict__ Ah, const bf16* __restrict__ Al,
    const bf16* __restrict__ Bh, const bf16* __restrict__ Bl,
    const float* __restrict__ bias, float* __restrict__ C,
    int M, int N, int K)
{
    extern __shared__ __align__(16) unsigned char smraw[];
    bf16* sm = reinterpret_cast<bf16*>(smraw);

    const int bx = blockIdx.x;     // N tile (256)
    const int by = blockIdx.y;     // M tile (128)
    const int tid = threadIdx.x;
    const int warp = tid >> 5;
    const int lane = tid & 31;
    const int warp_m = warp >> 2;      // 0..3  (32 rows)
    const int warp_n = warp & 3;       // 0..3  (64 cols)
    const int g  = lane >> 2;
    const int tg = lane & 3;

    const int nst = K / GBK;           // 64

    float acc[2][8][4];
    #pragma unroll
    for (int i = 0; i < 2; i++)
        #pragma unroll
        for (int j = 0; j < 8; j++)
            #pragma unroll
            for (int x = 0; x < 4; x++) acc[i][j][x] = 0.0f;

    auto issue = [&](int s) {
        const int k0 = s * GBK;
        bf16* buf = sm + (s % 3) * BUFSZ;
        // A: 128 rows x 4 chunks = 512 chunks per array, 1/thread each
        {
            int r = tid >> 2, c = tid & 3;
            size_t ga = (size_t)(by * 128 + r) * K + k0 + c * 8;
            int sa = r * SA + c * 8;
            cp_async16(buf + OAH + sa, Ah + ga);
            cp_async16(buf + OAL + sa, Al + ga);
        }
        // B: 32 rows x 32 chunks = 1024 chunks per array, 2/thread each
        #pragma unroll
        for (int p = 0; p < 2; p++) {
            int q = tid + p * 512;
            int r = q >> 5, c = q & 31;
            size_t gb = (size_t)(k0 + r) * N + bx * 256 + c * 8;
            int sb = r * SB + c * 8;
            cp_async16(buf + OBH + sb, Bh + gb);
            cp_async16(buf + OBL + sb, Bl + gb);
        }
    };

    issue(0); cp_commit();
    issue(1); cp_commit();

    const int a_row = lane & 15;
    const int a_colh = (lane >> 4) << 3;
    const int b_row = lane & 15;
    const int b_colh = (lane >> 4) << 3;

    for (int s = 0; s < nst; s++) {
        cp_wait<1>();
        __syncthreads();
        if (s + 2 < nst) { issue(s + 2); cp_commit(); }

        const bf16* buf = sm + (s % 3) * BUFSZ;

        #pragma unroll
        for (int ks = 0; ks < GBK; ks += 16) {
            uint32_t ah[2][4], al[2][4];
            #pragma unroll
            for (int i = 0; i < 2; i++) {
                int ra = (warp_m * 32 + i * 16 + a_row) * SA + ks + a_colh;
                ldmx4(ah[i], buf + OAH + ra);
                ldmx4(al[i], buf + OAL + ra);
            }
            #pragma unroll
            for (int jp = 0; jp < 4; jp++) {
                int rb = (ks + b_row) * SB + warp_n * 64 + jp * 16 + b_colh;
                uint32_t th[4], tl[4];
                ldmx4t(th, buf + OBH + rb);
                ldmx4t(tl, buf + OBL + rb);
                uint32_t b0h[2] = {th[0], th[1]}, b1h[2] = {th[2], th[3]};
                uint32_t b0l[2] = {tl[0], tl[1]}, b1l[2] = {tl[2], tl[3]};
                #pragma unroll
                for (int i = 0; i < 2; i++) {
                    mma16816(acc[i][2 * jp],     ah[i], b0h);
                    mma16816(acc[i][2 * jp],     ah[i], b0l);
                    mma16816(acc[i][2 * jp],     al[i], b0h);
                    mma16816(acc[i][2 * jp + 1], ah[i], b1h);
                    mma16816(acc[i][2 * jp + 1], ah[i], b1l);
                    mma16816(acc[i][2 * jp + 1], al[i], b1h);
                }
            }
        }
    }

    #pragma unroll
    for (int i = 0; i < 2; i++) {
        #pragma unroll
        for (int j = 0; j < 8; j++) {
            int row0 = by * 128 + warp_m * 32 + i * 16 + g;
            int col  = bx * 256 + warp_n * 64 + j * 8 + tg * 2;
            float b0 = bias[col], b1 = bias[col + 1];
            float2 v0 = make_float2(acc[i][j][0] + b0, acc[i][j][1] + b1);
            float2 v1 = make_float2(acc[i][j][2] + b0, acc[i][j][3] + b1);
            *reinterpret_cast<float2*>(C + (size_t)row0 * N + col) = v0;
            *reinterpret_cast<float2*>(C + (size_t)(row0 + 8) * N + col) = v1;
        }
    }
}

// ---------------- RoPE + scatter + bf16 hi/lo split ----------------
__global__ __launch_bounds__(128) void qkv_rope_split_kernel(
    const float* __restrict__ mixed,
    bf16* __restrict__ Qh, bf16* __restrict__ Ql,
    bf16* __restrict__ Kh, bf16* __restrict__ Kl,
    bf16* __restrict__ Vh, bf16* __restrict__ Vl)
{
    const int t = blockIdx.x;
    const int h = blockIdx.y;
    const int d = threadIdx.x;

    const float* base = mixed + (size_t)t * NQKV + h * (3 * HD);
    float q = base[d];
    float k = base[HD + d];
    float v = base[2 * HD + d];

    if (d < ROT) {
        const int i = d & 15;
        float inv_freq = 1.0f / powf(10000.0f, (float)(2 * i) * (1.0f / (float)ROT));
        float ang = (float)t * inv_freq;
        float s, c;
        sincosf(ang, &s, &c);
        if (d < 16) {
            q = q * c - base[d + 16] * s;
            k = k * c - base[HD + d + 16] * s;
        } else {
            q = q * c + base[d - 16] * s;
            k = k * c + base[HD + d - 16] * s;
        }
    }

    size_t off = ((size_t)h * S_LEN + t) * HD + d;
    bf16 qhi = __float2bfloat16(q);
    bf16 khi = __float2bfloat16(k);
    bf16 vhi = __float2bfloat16(v);
    Qh[off] = qhi;  Ql[off] = __float2bfloat16(q - __bfloat162float(qhi));
    Kh[off] = khi;  Kl[off] = __float2bfloat16(k - __bfloat162float(khi));
    Vh[off] = vhi;  Vl[off] = __float2bfloat16(v - __bfloat162float(vhi));
}

// ---------------- HMMA flash attention (bf16x3, causal) ----------------
#define FBM 128
#define FBN 64
#define FSTR 136

#define FQH 0
#define FQL (128 * FSTR)
#define FKV0 (2 * 128 * FSTR)
#define KVARR (64 * FSTR)
#define KVSTG (4 * KVARR)
#define FLASH_SMEM ((FKV0 + 2 * KVSTG) * 2)

__global__ __launch_bounds__(256, 1) void flash_mma_kernel(
    const bf16* __restrict__ Qh, const bf16* __restrict__ Ql,
    const bf16* __restrict__ Kh, const bf16* __restrict__ Kl,
    const bf16* __restrict__ Vh, const bf16* __restrict__ Vl,
    bf16* __restrict__ Ch, bf16* __restrict__ Cl)
{
    extern __shared__ __align__(16) unsigned char fsraw[];
    bf16* fs = reinterpret_cast<bf16*>(fsraw);

    const int h = blockIdx.y;
    const int m_tile = gridDim.x - 1 - blockIdx.x;
    const int m0 = m_tile * FBM;
    const int tid = threadIdx.x;
    const int warp = tid >> 5;
    const int lane = tid & 31;
    const int g  = lane >> 2;
    const int tg = lane & 3;

    const bf16* qhp = Qh + ((size_t)h * S_LEN + m0) * HD;
    const bf16* qlp = Ql + ((size_t)h * S_LEN + m0) * HD;
    const bf16* khp = Kh + (size_t)h * S_LEN * HD;
    const bf16* klp = Kl + (size_t)h * S_LEN * HD;
    const bf16* vhp = Vh + (size_t)h * S_LEN * HD;
    const bf16* vlp = Vl + (size_t)h * S_LEN * HD;

    for (int idx = tid; idx < 2048; idx += 256) {
        int r = idx >> 4, c = (idx & 15) << 3;
        *reinterpret_cast<float4*>(fs + FQH + r * FSTR + c) =
            *reinterpret_cast<const float4*>(qhp + (size_t)r * HD + c);
        *reinterpret_cast<float4*>(fs + FQL + r * FSTR + c) =
            *reinterpret_cast<const float4*>(qlp + (size_t)r * HD + c);
    }

    auto issue_kv = [&](int nt) {
        const int n0 = nt * FBN;
        bf16* buf = fs + FKV0 + (nt & 1) * KVSTG;
        #pragma unroll
        for (int q = tid; q < 1024; q += 256) {
            int r = q >> 4, c = (q & 15) << 3;
            size_t go = (size_t)(n0 + r) * HD + c;
            int so = r * FSTR + c;
            cp_async16(buf + 0 * KVARR + so, khp + go);
            cp_async16(buf + 1 * KVARR + so, klp + go);
            cp_async16(buf + 2 * KVARR + so, vhp + go);
            cp_async16(buf + 3 * KVARR + so, vlp + go);
        }
    };

    float o[16][4];
    #pragma unroll
    for (int j = 0; j < 16; j++)
        #pragma unroll
        for (int x = 0; x < 4; x++) o[j][x] = 0.0f;
    float mrow0 = -1e30f, mrow1 = -1e30f, lrow0 = 0.0f, lrow1 = 0.0f;

    const float scale = 0.08838834764831845f;
    const int row0 = m0 + warp * 16 + g;
    const int row1 = row0 + 8;
    const int wrow_max = m0 + warp * 16 + 15;

    const int a_row = lane & 15;
    const int half8 = (lane >> 4) << 3;
    const int bk_colh = ((lane >> 3) & 1) << 3;

    const int ntiles = m0 / FBN + 2;
    issue_kv(0); cp_commit();

    for (int nt = 0; nt < ntiles; nt++) {
        const int n0 = nt * FBN;
        if (nt + 1 < ntiles) { issue_kv(nt + 1); cp_commit(); cp_wait<1>(); }
        else                 { cp_wait<0>(); }
        __syncthreads();

        if (n0 <= wrow_max) {
            const bf16* kvb = fs + FKV0 + (nt & 1) * KVSTG;
            const bf16* kh_s = kvb;
            const bf16* kl_s = kvb + KVARR;
            const bf16* vh_s = kvb + 2 * KVARR;
            const bf16* vl_s = kvb + 3 * KVARR;

            float sacc[8][4];
            #pragma unroll
            for (int j = 0; j < 8; j++)
                #pragma unroll
                for (int x = 0; x < 4; x++) sacc[j][x] = 0.0f;

            #pragma unroll
            for (int ks = 0; ks < 8; ks++) {
                const int k = ks * 16;
                uint32_t aH[4], aL[4];
                {
                    int ra = (warp * 16 + a_row) * FSTR + k + half8;
                    ldmx4(aH, fs + FQH + ra);
                    ldmx4(aL, fs + FQL + ra);
                }
                #pragma unroll
                for (int jp = 0; jp < 4; jp++) {
                    int rb = (jp * 16 + half8 + (lane & 7)) * FSTR + k + bk_colh;
                    uint32_t bH[4], bL[4];
                    ldmx4(bH, kh_s + rb);
                    ldmx4(bL, kl_s + rb);
                    uint32_t b0h[2] = {bH[0], bH[1]}, b1h[2] = {bH[2], bH[3]};
                    uint32_t b0l[2] = {bL[0], bL[1]}, b1l[2] = {bL[2], bL[3]};
                    mma16816(sacc[2 * jp],     aH, b0h);
                    mma16816(sacc[2 * jp],     aH, b0l);
                    mma16816(sacc[2 * jp],     aL, b0h);
                    mma16816(sacc[2 * jp + 1], aH, b1h);
                    mma16816(sacc[2 * jp + 1], aH, b1l);
                    mma16816(sacc[2 * jp + 1], aL, b1h);
                }
            }

            const bool boundary = (n0 + FBN - 1 > m0);
            #pragma unroll
            for (int j = 0; j < 8; j++) {
                int c0 = n0 + j * 8 + 2 * tg;
                if (boundary) {
                    sacc[j][0] = (c0     > row0) ? -1e30f : sacc[j][0] * scale;
                    sacc[j][1] = (c0 + 1 > row0) ? -1e30f : sacc[j][1] * scale;
                    sacc[j][2] = (c0     > row1) ? -1e30f : sacc[j][2] * scale;
                    sacc[j][3] = (c0 + 1 > row1) ? -1e30f : sacc[j][3] * scale;
                } else {
                    sacc[j][0] *= scale; sacc[j][1] *= scale;
                    sacc[j][2] *= scale; sacc[j][3] *= scale;
                }
            }

            float mx0 = -1e30f, mx1 = -1e30f;
            #pragma unroll
            for (int j = 0; j < 8; j++) {
                mx0 = fmaxf(mx0, fmaxf(sacc[j][0], sacc[j][1]));
                mx1 = fmaxf(mx1, fmaxf(sacc[j][2], sacc[j][3]));
            }
            mx0 = fmaxf(mx0, __shfl_xor_sync(0xffffffffu, mx0, 1));
            mx0 = fmaxf(mx0, __shfl_xor_sync(0xffffffffu, mx0, 2));
            mx1 = fmaxf(mx1, __shfl_xor_sync(0xffffffffu, mx1, 1));
            mx1 = fmaxf(mx1, __shfl_xor_sync(0xffffffffu, mx1, 2));

            float mn0 = fmaxf(mrow0, mx0);
            float mn1 = fmaxf(mrow1, mx1);
            float alpha0 = __expf(mrow0 - mn0);
            float alpha1 = __expf(mrow1 - mn1);
            mrow0 = mn0; mrow1 = mn1;

            float sum0 = 0.0f, sum1 = 0.0f;
            #pragma unroll
            for (int j = 0; j < 8; j++) {
                sacc[j][0] = __expf(sacc[j][0] - mn0);
                sacc[j][1] = __expf(sacc[j][1] - mn0);
                sacc[j][2] = __expf(sacc[j][2] - mn1);
                sacc[j][3] = __expf(sacc[j][3] - mn1);
                sum0 += sacc[j][0] + sacc[j][1];
                sum1 += sacc[j][2] + sacc[j][3];
            }
            sum0 += __shfl_xor_sync(0xffffffffu, sum0, 1);
            sum0 += __shfl_xor_sync(0xffffffffu, sum0, 2);
            sum1 += __shfl_xor_sync(0xffffffffu, sum1, 1);
            sum1 += __shfl_xor_sync(0xffffffffu, sum1, 2);
            lrow0 = lrow0 * alpha0 + sum0;
            lrow1 = lrow1 * alpha1 + sum1;

            #pragma unroll
            for (int j = 0; j < 16; j++) {
                o[j][0] *= alpha0; o[j][1] *= alpha0;
                o[j][2] *= alpha1; o[j][3] *= alpha1;
            }

            #pragma unroll
            for (int kk = 0; kk < 4; kk++) {
                uint32_t paH[4], paL[4];
                #pragma unroll
                for (int half = 0; half < 2; half++) {
                    const float* sv = sacc[2 * kk + half];
                    __nv_bfloat162 h0 = __floats2bfloat162_rn(sv[0], sv[1]);
                    __nv_bfloat162 h1 = __floats2bfloat162_rn(sv[2], sv[3]);
                    __nv_bfloat162 l0 = __floats2bfloat162_rn(
                        sv[0] - __bfloat162float(h0.x), sv[1] - __bfloat162float(h0.y));
                    __nv_bfloat162 l1 = __floats2bfloat162_rn(
                        sv[2] - __bfloat162float(h1.x), sv[3] - __bfloat162float(h1.y));
                    paH[2 * half]     = *reinterpret_cast<uint32_t*>(&h0);
                    paH[2 * half + 1] = *reinterpret_cast<uint32_t*>(&h1);
                    paL[2 * half]     = *reinterpret_cast<uint32_t*>(&l0);
                    paL[2 * half + 1] = *reinterpret_cast<uint32_t*>(&l1);
                }
                #pragma unroll
                for (int jp = 0; jp < 8; jp++) {
                    int rv = (kk * 16 + a_row) * FSTR + jp * 16 + half8;
                    uint32_t vH[4], vL[4];
                    ldmx4t(vH, vh_s + rv);
                    ldmx4t(vL, vl_s + rv);
                    uint32_t v0h[2] = {vH[0], vH[1]}, v1h[2] = {vH[2], vH[3]};
                    uint32_t v0l[2] = {vL[0], vL[1]}, v1l[2] = {vL[2], vL[3]};
                    mma16816(o[2 * jp],     paH, v0h);
                    mma16816(o[2 * jp],     paH, v0l);
                    mma16816(o[2 * jp],     paL, v0h);
                    mma16816(o[2 * jp + 1], paH, v1h);
                    mma16816(o[2 * jp + 1], paH, v1l);
                    mma16816(o[2 * jp + 1], paL, v1h);
                }
            }
        }
        __syncthreads();
    }

    float inv0 = 1.0f / lrow0;
    float inv1 = 1.0f / lrow1;
    #pragma unroll
    for (int jt = 0; jt < 16; jt++) {
        int col = h * HD + jt * 8 + 2 * tg;
        float v00 = o[jt][0] * inv0, v01 = o[jt][1] * inv0;
        float v10 = o[jt][2] * inv1, v11 = o[jt][3] * inv1;
        __nv_bfloat162 h0 = __floats2bfloat162_rn(v00, v01);
        __nv_bfloat162 h1 = __floats2bfloat162_rn(v10, v11);
        __nv_bfloat162 l0 = __floats2bfloat162_rn(
            v00 - __bfloat162float(h0.x), v01 - __bfloat162float(h0.y));
        __nv_bfloat162 l1 = __floats2bfloat162_rn(
            v10 - __bfloat162float(h1.x), v11 - __bfloat162float(h1.y));
        *reinterpret_cast<__nv_bfloat162*>(Ch + (size_t)row0 * HID + col) = h0;
        *reinterpret_cast<__nv_bfloat162*>(Cl + (size_t)row0 * HID + col) = l0;
        *reinterpret_cast<__nv_bfloat162*>(Ch + (size_t)row1 * HID + col) = h1;
        *reinterpret_cast<__nv_bfloat162*>(Cl + (size_t)row1 * HID + col) = l1;
    }
}

// ---------------- launch ----------------
extern "C" void kernel_launch(void* const* d_in, const int* in_sizes, int n_in,
                              void* d_out, int out_size)
{
    const float* hidden  = (const float*)d_in[0];
    const float* W_qkv   = (const float*)d_in[1];
    const float* b_qkv   = (const float*)d_in[2];
    const float* W_dense = (const float*)d_in[3];
    const float* b_dense = (const float*)d_in[4];
    float* out = (float*)d_out;

    float *mixed;
    bf16 *ah, *al, *bh, *bl, *wh, *wl, *ch, *cl;
    bf16 *qh, *ql, *kh, *kl, *vh, *vl;
    cudaGetSymbolAddress((void**)&mixed, g_mixed);
    cudaGetSymbolAddress((void**)&ah,    g_ah);
    cudaGetSymbolAddress((void**)&al,    g_al);
    cudaGetSymbolAddress((void**)&bh,    g_bh);
    cudaGetSymbolAddress((void**)&bl,    g_bl);
    cudaGetSymbolAddress((void**)&wh,    g_wh);
    cudaGetSymbolAddress((void**)&wl,    g_wl);
    cudaGetSymbolAddress((void**)&ch,    g_ch);
    cudaGetSymbolAddress((void**)&cl,    g_cl);
    cudaGetSymbolAddress((void**)&qh,    g_qh);
    cudaGetSymbolAddress((void**)&ql,    g_ql);
    cudaGetSymbolAddress((void**)&kh,    g_kh);
    cudaGetSymbolAddress((void**)&kl,    g_kl);
    cudaGetSymbolAddress((void**)&vh,    g_vh);
    cudaGetSymbolAddress((void**)&vl,    g_vl);

    cudaFuncSetAttribute(mma_gemm_bf16x3,
                         cudaFuncAttributeMaxDynamicSharedMemorySize, GEMM_SMEM);
    cudaFuncSetAttribute(flash_mma_kernel,
                         cudaFuncAttributeMaxDynamicSharedMemorySize, FLASH_SMEM);

    // 0) bf16 hi/lo splits
    {
        int n4 = S_LEN * HID / 4;
        split_bf16_kernel<<<(n4 + 255) / 256, 256>>>(hidden, ah, al, n4);
        int w4 = HID * NQKV / 4;
        split_bf16_kernel<<<(w4 + 255) / 256, 256>>>(W_qkv, bh, bl, w4);
        int d4 = HID * HID / 4;
        split_bf16_kernel<<<(d4 + 255) / 256, 256>>>(W_dense, wh, wl, d4);
    }

    // 1) QKV projection (+bias)
    {
        dim3 grid(NQKV / 256, S_LEN / 128);
        mma_gemm_bf16x3<<<grid, 512, GEMM_SMEM>>>(ah, al, bh, bl, b_qkv, mixed,
                                                  S_LEN, NQKV, HID);
    }

    // 2) RoPE + scatter + split
    qkv_rope_split_kernel<<<dim3(S_LEN, NH), 128>>>(mixed, qh, ql, kh, kl, vh, vl);

    // 3) causal flash attention; writes ctx bf16 hi/lo
    flash_mma_kernel<<<dim3(S_LEN / FBM, NH), 256, FLASH_SMEM>>>(
        qh, ql, kh, kl, vh, vl, ch, cl);

    // 4) dense projection (+bias)
    {
        dim3 grid(HID / 256, S_LEN / 128);
        mma_gemm_bf16x3<<<grid, 512, GEMM_SMEM>>>(ch, cl, wh, wl, b_dense, out,
                                                  S_LEN, HID, HID);
    }
}